// round 6
// baseline (speedup 1.0000x reference)
#include <cuda_runtime.h>
#include <cstdint>
#include <math.h>

#define BATCH 4
#define SEQ   4096
#define FEAT  1024
#define HID   1024

// ---------------------------------------------------------------------------
// Scratch (device globals — allocation-free per harness rules)
// All MMA k-dims stored sigma-permuted within 8-groups: [0,4,1,5,2,6,3,7]
// ---------------------------------------------------------------------------
__device__ float g_xc [BATCH * SEQ * FEAT];   // x  (tf32, sigma-f)    64 MB
__device__ float g_wqt[FEAT * HID];           // Wq^T (tf32, sigma-f)   4 MB
__device__ float g_wkt[FEAT * HID];           // Wk^T (tf32, sigma-f)   4 MB
__device__ float g_wvt[FEAT * HID];           // Wv^T (tf32, sigma-f)   4 MB
__device__ float g_q  [BATCH * SEQ * HID];    // Q (tf32, sigma-h)     64 MB
__device__ float g_k  [BATCH * SEQ * HID];    // K (tf32, sigma-h)     64 MB
__device__ float g_v  [BATCH * SEQ * HID];    // V (natural h)         64 MB
__device__ float g_vt [BATCH * HID * SEQ];    // V^T (tf32, sigma-s)   64 MB
__device__ float g_p  [(size_t)BATCH * SEQ * SEQ]; // exp(scores)     256 MB
__device__ float g_rs [BATCH * SEQ];          // row sums of exp

// ---------------------------------------------------------------------------
__device__ __forceinline__ float to_tf32(float x) {
    uint32_t u;
    asm("cvt.rn.tf32.f32 %0, %1;" : "=r"(u) : "f"(x));
    return __uint_as_float(u);
}

__device__ __forceinline__ void cp_async16(uint32_t s, const float* g) {
    asm volatile("cp.async.cg.shared.global [%0], [%1], 16;"
                 :: "r"(s), "l"(__cvta_generic_to_global((const void*)g)) : "memory");
}

__device__ __forceinline__ uint32_t smem_u32(const void* p) {
    uint32_t a;
    asm("{ .reg .u64 t; cvta.to.shared.u64 t, %1; cvt.u32.u64 %0, t; }"
        : "=r"(a) : "l"(p));
    return a;
}

__device__ __forceinline__ void mma_tf32(float* c, float2 a01, float2 a23, float2 b) {
    asm volatile(
        "mma.sync.aligned.m16n8k8.row.col.f32.tf32.tf32.f32 "
        "{%0,%1,%2,%3}, {%4,%5,%6,%7}, {%8,%9}, {%0,%1,%2,%3};"
        : "+f"(c[0]), "+f"(c[1]), "+f"(c[2]), "+f"(c[3])
        : "r"(__float_as_uint(a01.x)), "r"(__float_as_uint(a23.x)),
          "r"(__float_as_uint(a01.y)), "r"(__float_as_uint(a23.y)),
          "r"(__float_as_uint(b.x)),   "r"(__float_as_uint(b.y)));
}

// ---------------------------------------------------------------------------
// tf32 mma.sync GEMM (NT), sigma-k layout. BM=128,BN=256,BK=32, 3 stages.
// Fragments double-buffered across kk-steps (LDS latency hidden by MMAs).
// Epilogue MODE: 0 = bias + tf32-round + sigma-store (Q/K)
//               1 = bias + natural store (V)
//               2 = exp(alpha*acc) + tf32-round + sigma-store + rowsum (scores)
//               3 = acc / rowsum, natural store (output)
// ---------------------------------------------------------------------------
#define GBM 128
#define GBN 256
#define GBK 32
#define GST 3
#define AST 40
#define A_FLTS (GBM * AST)
#define B_FLTS (GBN * AST)
#define STAGE_FLTS (A_FLTS + B_FLTS)
#define GEMM_SMEM (GST * STAGE_FLTS * 4)

struct Frag {
    float2 a[4][2];
    float2 b[8];
};

template <int MODE>
__global__ __launch_bounds__(256, 1)
void gemm_mma(const float* __restrict__ A, const float* __restrict__ B,
              const float* __restrict__ bias, float* __restrict__ C,
              float* __restrict__ rowsum,
              int K, int ldc, float alpha,
              long long sA, long long sB, long long sC)
{
    extern __shared__ float sm[];
    const uint32_t sbase = smem_u32(sm);

    const int tid = threadIdx.x;
    const int wid = tid >> 5, lane = tid & 31;
    const int g = lane >> 2, t = lane & 3;
    const int wm = wid >> 2, wn = wid & 3;
    const int wm0 = wm * 64, wn0 = wn * 64;

    const int bz = blockIdx.z;
    A += sA * bz; B += sB * bz; C += sC * bz;
    if (MODE == 2 || MODE == 3) rowsum += (long long)SEQ * bz;   // per-batch rowsums
    const int m0 = blockIdx.y * GBM;
    const int n0 = blockIdx.x * GBN;

    const int NITER = K / GBK;

    auto load_stage = [&](int c) {
        const int slot = c % GST;
        const uint32_t s_a = sbase + slot * STAGE_FLTS * 4;
        const uint32_t s_b = s_a + A_FLTS * 4;
        const long long koff = (long long)c * GBK;
        #pragma unroll
        for (int i = 0; i < 4; i++) {
            int s = tid + i * 256;
            int row = s >> 3, ch = s & 7;
            cp_async16(s_a + (uint32_t)(row * AST + ch * 4) * 4,
                       A + (long long)(m0 + row) * K + koff + ch * 4);
        }
        #pragma unroll
        for (int i = 0; i < 8; i++) {
            int s = tid + i * 256;
            int row = s >> 3, ch = s & 7;
            cp_async16(s_b + (uint32_t)(row * AST + ch * 4) * 4,
                       B + (long long)(n0 + row) * K + koff + ch * 4);
        }
        asm volatile("cp.async.commit_group;" ::: "memory");
    };

    float acc[4][8][4];
    #pragma unroll
    for (int mi = 0; mi < 4; mi++)
        #pragma unroll
        for (int ni = 0; ni < 8; ni++)
            #pragma unroll
            for (int r = 0; r < 4; r++) acc[mi][ni][r] = 0.f;

    load_stage(0);
    if (NITER > 1) load_stage(1);

    Frag fr[2];

    for (int it = 0; it < NITER; it++) {
        if (it < NITER - 1)
            asm volatile("cp.async.wait_group 1;" ::: "memory");
        else
            asm volatile("cp.async.wait_group 0;" ::: "memory");
        __syncthreads();

        const int slot = it % GST;
        const float* as = sm + slot * STAGE_FLTS + wm0 * AST;
        const float* bs = sm + slot * STAGE_FLTS + A_FLTS + wn0 * AST;

        auto load_frag = [&](int kk, Frag& f) {
            const int kc = kk * 8 + 2 * t;          // sigma layout: (t, t+4) adjacent
            #pragma unroll
            for (int mi = 0; mi < 4; mi++) {
                const float* ap = as + (mi * 16 + g) * AST + kc;
                f.a[mi][0] = *(const float2*)ap;              // rows g    -> a0, a2
                f.a[mi][1] = *(const float2*)(ap + 8 * AST);  // rows g+8  -> a1, a3
            }
            #pragma unroll
            for (int ni = 0; ni < 8; ni++)
                f.b[ni] = *(const float2*)(bs + (ni * 8 + g) * AST + kc);
        };

        // prime kk=0 fragments, then issue next-stage cp.async behind them
        load_frag(0, fr[0]);
        if (it + 2 < NITER) load_stage(it + 2);

        #pragma unroll
        for (int kk = 0; kk < 4; kk++) {
            if (kk < 3) load_frag(kk + 1, fr[(kk + 1) & 1]);
            Frag& f = fr[kk & 1];
            #pragma unroll
            for (int mi = 0; mi < 4; mi++)
                #pragma unroll
                for (int ni = 0; ni < 8; ni++)
                    mma_tf32(acc[mi][ni], f.a[mi][0], f.a[mi][1], f.b[ni]);
        }
    }

    // ---------------- epilogue ----------------
    // sigma positions for logical cols (2t, 2t+1) within an 8-group:
    const int p0 = (t < 2) ? 4 * t : 4 * t - 7;   // logical 2t
    const int p1 = p0 + 2;                         // logical 2t+1

    if (MODE == 3) {
        #pragma unroll
        for (int mi = 0; mi < 4; mi++) {
            const int row0 = m0 + wm0 + mi * 16 + g;
            const float i0 = 1.0f / rowsum[row0];
            const float i8 = 1.0f / rowsum[row0 + 8];
            #pragma unroll
            for (int ni = 0; ni < 8; ni++) {
                const int col = n0 + wn0 + ni * 8 + 2 * t;
                *(float2*)(C + (long long)row0 * ldc + col) =
                    make_float2(acc[mi][ni][0] * i0, acc[mi][ni][1] * i0);
                *(float2*)(C + (long long)(row0 + 8) * ldc + col) =
                    make_float2(acc[mi][ni][2] * i8, acc[mi][ni][3] * i8);
            }
        }
    } else if (MODE == 2) {
        #pragma unroll
        for (int mi = 0; mi < 4; mi++) {
            const int row0 = m0 + wm0 + mi * 16 + g;
            float s0 = 0.f, s8 = 0.f;
            #pragma unroll
            for (int ni = 0; ni < 8; ni++) {
                const int ng = n0 + wn0 + ni * 8;
                float e0 = to_tf32(__expf(alpha * acc[mi][ni][0]));
                float e1 = to_tf32(__expf(alpha * acc[mi][ni][1]));
                float e2 = to_tf32(__expf(alpha * acc[mi][ni][2]));
                float e3 = to_tf32(__expf(alpha * acc[mi][ni][3]));
                s0 += e0 + e1;  s8 += e2 + e3;
                float* r0p = C + (long long)row0 * ldc + ng;
                float* r8p = C + (long long)(row0 + 8) * ldc + ng;
                r0p[p0] = e0;  r0p[p1] = e1;
                r8p[p0] = e2;  r8p[p1] = e3;
            }
            s0 += __shfl_xor_sync(0xffffffffu, s0, 1);
            s0 += __shfl_xor_sync(0xffffffffu, s0, 2);
            s8 += __shfl_xor_sync(0xffffffffu, s8, 1);
            s8 += __shfl_xor_sync(0xffffffffu, s8, 2);
            if (t == 0) {
                atomicAdd(&rowsum[row0], s0);
                atomicAdd(&rowsum[row0 + 8], s8);
            }
        }
    } else {
        #pragma unroll
        for (int mi = 0; mi < 4; mi++) {
            const int row0 = m0 + wm0 + mi * 16 + g;
            #pragma unroll
            for (int ni = 0; ni < 8; ni++) {
                const int ng = n0 + wn0 + ni * 8;
                const float2 bv = *(const float2*)(bias + ng + 2 * t);
                float v0 = acc[mi][ni][0] + bv.x;
                float v1 = acc[mi][ni][1] + bv.y;
                float v2 = acc[mi][ni][2] + bv.x;
                float v3 = acc[mi][ni][3] + bv.y;
                if (MODE == 0) {
                    v0 = to_tf32(v0); v1 = to_tf32(v1);
                    v2 = to_tf32(v2); v3 = to_tf32(v3);
                    float* r0p = C + (long long)row0 * ldc + ng;
                    float* r8p = C + (long long)(row0 + 8) * ldc + ng;
                    r0p[p0] = v0;  r0p[p1] = v1;
                    r8p[p0] = v2;  r8p[p1] = v3;
                } else {
                    const int col = ng + 2 * t;
                    *(float2*)(C + (long long)row0 * ldc + col) = make_float2(v0, v1);
                    *(float2*)(C + (long long)(row0 + 8) * ldc + col) = make_float2(v2, v3);
                }
            }
        }
    }
}

// ---------------------------------------------------------------------------
// x -> tf32 + sigma-permute k within 8-groups: mem order [0,4,1,5,2,6,3,7]
// ---------------------------------------------------------------------------
__global__ __launch_bounds__(256)
void convert_sigma_kernel(const float4* __restrict__ in, float4* __restrict__ out, int n8)
{
    int i = blockIdx.x * 256 + threadIdx.x;
    if (i < n8) {
        float4 v0 = in[i * 2], v1 = in[i * 2 + 1];
        float4 o0 = make_float4(to_tf32(v0.x), to_tf32(v1.x), to_tf32(v0.y), to_tf32(v1.y));
        float4 o1 = make_float4(to_tf32(v0.z), to_tf32(v1.z), to_tf32(v0.w), to_tf32(v1.w));
        out[i * 2] = o0;
        out[i * 2 + 1] = o1;
    }
}

// ---------------------------------------------------------------------------
// Transpose + tf32 round + sigma-permute the (output-row-index = k) dim.
// in [R x Cc], out [Cc x R] with out[c][sigp(r)] = tf32(in[r][c])
// ---------------------------------------------------------------------------
__global__ __launch_bounds__(256)
void transpose_sigma(const float* __restrict__ in, float* __restrict__ out,
                     int R, int Cc, long long sIn, long long sOut)
{
    __shared__ float tbuf[32][33];
    const int bz = blockIdx.z;
    in += sIn * bz; out += sOut * bz;
    const int c0 = blockIdx.x * 32, r0 = blockIdx.y * 32;
    const int x = threadIdx.x, y = threadIdx.y;   // (32, 8)
    #pragma unroll
    for (int i = 0; i < 32; i += 8)
        tbuf[y + i][x] = in[(long long)(r0 + y + i) * Cc + c0 + x];
    __syncthreads();
    const int j = x & 7;
    const int sx = (x & ~7) | ((j < 4) ? (2 * j) : (2 * (j - 4) + 1));
    #pragma unroll
    for (int i = 0; i < 32; i += 8)
        out[(long long)(c0 + y + i) * R + r0 + sx] = to_tf32(tbuf[x][y + i]);
}

__global__ __launch_bounds__(256)
void zero_kernel(float* __restrict__ p, int n)
{
    int i = blockIdx.x * 256 + threadIdx.x;
    if (i < n) p[i] = 0.f;
}

// ---------------------------------------------------------------------------
extern "C" void kernel_launch(void* const* d_in, const int* in_sizes, int n_in,
                              void* d_out, int out_size)
{
    const float* x  = (const float*)d_in[0];
    const float* Wq = (const float*)d_in[1];
    const float* bq = (const float*)d_in[2];
    const float* Wk = (const float*)d_in[3];
    const float* bk = (const float*)d_in[4];
    const float* Wv = (const float*)d_in[5];
    const float* bv = (const float*)d_in[6];
    float* out = (float*)d_out;

    float *xc, *wqt, *wkt, *wvt, *q, *k, *v, *vt, *p, *rs;
    cudaGetSymbolAddress((void**)&xc,  g_xc);
    cudaGetSymbolAddress((void**)&wqt, g_wqt);
    cudaGetSymbolAddress((void**)&wkt, g_wkt);
    cudaGetSymbolAddress((void**)&wvt, g_wvt);
    cudaGetSymbolAddress((void**)&q,   g_q);
    cudaGetSymbolAddress((void**)&k,   g_k);
    cudaGetSymbolAddress((void**)&v,   g_v);
    cudaGetSymbolAddress((void**)&vt,  g_vt);
    cudaGetSymbolAddress((void**)&p,   g_p);
    cudaGetSymbolAddress((void**)&rs,  g_rs);

    cudaFuncSetAttribute(gemm_mma<0>, cudaFuncAttributeMaxDynamicSharedMemorySize, GEMM_SMEM);
    cudaFuncSetAttribute(gemm_mma<1>, cudaFuncAttributeMaxDynamicSharedMemorySize, GEMM_SMEM);
    cudaFuncSetAttribute(gemm_mma<2>, cudaFuncAttributeMaxDynamicSharedMemorySize, GEMM_SMEM);
    cudaFuncSetAttribute(gemm_mma<3>, cudaFuncAttributeMaxDynamicSharedMemorySize, GEMM_SMEM);

    // 0) zero rowsums + convert x (tf32 + sigma)
    zero_kernel<<<(BATCH * SEQ + 255) / 256, 256>>>(rs, BATCH * SEQ);
    convert_sigma_kernel<<<(BATCH * SEQ * FEAT / 8 + 255) / 256, 256>>>(
        (const float4*)x, (float4*)xc, BATCH * SEQ * FEAT / 8);

    // 1) W transposes (tf32 + sigma on f)
    dim3 tw(HID / 32, FEAT / 32, 1);
    transpose_sigma<<<tw, dim3(32, 8)>>>(Wq, wqt, FEAT, HID, 0, 0);
    transpose_sigma<<<tw, dim3(32, 8)>>>(Wk, wkt, FEAT, HID, 0, 0);
    transpose_sigma<<<tw, dim3(32, 8)>>>(Wv, wvt, FEAT, HID, 0, 0);

    // 2) QKV projections
    dim3 gqkv(HID / GBN, (BATCH * SEQ) / GBM, 1);
    gemm_mma<0><<<gqkv, 256, GEMM_SMEM>>>(xc, wqt, bq, q, nullptr, FEAT, HID, 1.0f, 0, 0, 0);
    gemm_mma<0><<<gqkv, 256, GEMM_SMEM>>>(xc, wkt, bk, k, nullptr, FEAT, HID, 1.0f, 0, 0, 0);
    gemm_mma<1><<<gqkv, 256, GEMM_SMEM>>>(xc, wvt, bv, v, nullptr, FEAT, HID, 1.0f, 0, 0, 0);

    // 3) p = exp((Q K^T)/32) (sigma-stored) + rowsums
    dim3 gs(SEQ / GBN, SEQ / GBM, BATCH);
    gemm_mma<2><<<gs, 256, GEMM_SMEM>>>(q, k, nullptr, p, rs, HID, SEQ, 1.0f / 32.0f,
                                        (long long)SEQ * HID, (long long)SEQ * HID,
                                        (long long)SEQ * SEQ);

    // 4) V^T (tf32 + sigma on s)
    dim3 tv(HID / 32, SEQ / 32, BATCH);
    transpose_sigma<<<tv, dim3(32, 8)>>>(v, vt, SEQ, HID,
                                         (long long)SEQ * HID, (long long)HID * SEQ);

    // 5) out = (P V) / rowsum
    dim3 go(HID / GBN, SEQ / GBM, BATCH);
    gemm_mma<3><<<go, 256, GEMM_SMEM>>>(p, vt, nullptr, out, rs, SEQ, HID, 1.0f,
                                        (long long)SEQ * SEQ, (long long)HID * SEQ,
                                        (long long)SEQ * HID);
}

// round 7
// speedup vs baseline: 1.9351x; 1.9351x over previous
#include <cuda_runtime.h>
#include <cuda_fp16.h>
#include <cstdint>
#include <math.h>

#define BATCH 4
#define SEQ   4096
#define FEAT  1024
#define HID   1024

// ---------------------------------------------------------------------------
// Scratch (device globals). All fp16 MMA operands stored sigma16-permuted
// within 16-k-groups: mem order [0,1,8,9, 2,3,10,11, 4,5,12,13, 6,7,14,15]
// ---------------------------------------------------------------------------
__device__ __half g_xc [BATCH * SEQ * FEAT];   // x   (fp16, sig-f)   32 MB
__device__ __half g_wqt[FEAT * HID];           // Wq^T (fp16, sig-f)   2 MB
__device__ __half g_wkt[FEAT * HID];           // Wk^T (fp16, sig-f)   2 MB
__device__ __half g_wvt[FEAT * HID];           // Wv^T (fp16, sig-f)   2 MB
__device__ __half g_q  [BATCH * SEQ * HID];    // Q (fp16, sig-h)     32 MB
__device__ __half g_k  [BATCH * SEQ * HID];    // K (fp16, sig-h)     32 MB
__device__ float  g_v  [BATCH * SEQ * HID];    // V (f32 natural)     64 MB
__device__ __half g_vt [BATCH * HID * SEQ];    // V^T (fp16, sig-s)   32 MB
__device__ __half g_p  [(size_t)BATCH * SEQ * SEQ]; // exp(scores)   128 MB
__device__ float  g_rs [BATCH * SEQ];          // row sums of exp

// ---------------------------------------------------------------------------
__device__ __forceinline__ uint32_t pack2(float lo, float hi) {
    __half2 h = __floats2half2_rn(lo, hi);
    return *reinterpret_cast<uint32_t*>(&h);
}
__device__ __forceinline__ float2 unpack2(uint32_t u) {
    __half2 h = *reinterpret_cast<__half2*>(&u);
    return __half22float2(h);
}

__device__ __forceinline__ void cp_async16(uint32_t s, const void* g) {
    asm volatile("cp.async.cg.shared.global [%0], [%1], 16;"
                 :: "r"(s), "l"(__cvta_generic_to_global(g)) : "memory");
}

__device__ __forceinline__ uint32_t smem_u32(const void* p) {
    uint32_t a;
    asm("{ .reg .u64 t; cvta.to.shared.u64 t, %1; cvt.u32.u64 %0, t; }"
        : "=r"(a) : "l"(p));
    return a;
}

__device__ __forceinline__ void mma_f16(float* c, uint32_t a0, uint32_t a1,
                                        uint32_t a2, uint32_t a3,
                                        uint32_t b0, uint32_t b1) {
    asm volatile(
        "mma.sync.aligned.m16n8k16.row.col.f32.f16.f16.f32 "
        "{%0,%1,%2,%3}, {%4,%5,%6,%7}, {%8,%9}, {%0,%1,%2,%3};"
        : "+f"(c[0]), "+f"(c[1]), "+f"(c[2]), "+f"(c[3])
        : "r"(a0), "r"(a1), "r"(a2), "r"(a3), "r"(b0), "r"(b1));
}

// ---------------------------------------------------------------------------
// fp16 mma.sync GEMM (NT), sigma16-k layout.
// BM=128, BN=256, BK=64 halves, 3 stages, 256 threads (8 warps 2x4 -> 64x64).
// Row stride in smem = 80 halves (160B): conflict-free LDS.64 fragments.
// Epilogue MODE: 0 = bias + fp16 + sigma16-store (Q/K)
//               1 = bias + f32 natural store (V)
//               2 = exp(alpha*acc) -> fp16 sigma16-store + rowsum (probs)
//               3 = acc / rowsum, f32 natural store (output)
// ---------------------------------------------------------------------------
#define GBM 128
#define GBN 256
#define GBK 64                                  // halves per k-iter
#define GST 3
#define SROW 80                                 // halves per smem row (64+16 pad)
#define A_HALVES (GBM * SROW)                   // 10240
#define B_HALVES (GBN * SROW)                   // 20480
#define STG_HALVES (A_HALVES + B_HALVES)        // 30720
#define GEMM_SMEM (GST * STG_HALVES * 2)        // 184320 bytes

template <int MODE>
__global__ __launch_bounds__(256, 1)
void gemm_mma(const __half* __restrict__ A, const __half* __restrict__ B,
              const float* __restrict__ bias, void* __restrict__ Cv,
              float* __restrict__ rowsum,
              int K, int ldc, float alpha,
              long long sA, long long sB, long long sC)
{
    extern __shared__ __half smh[];
    const uint32_t sbase = smem_u32(smh);

    const int tid = threadIdx.x;
    const int wid = tid >> 5, lane = tid & 31;
    const int g = lane >> 2, t = lane & 3;
    const int wm = wid >> 2, wn = wid & 3;
    const int wm0 = wm * 64, wn0 = wn * 64;

    const int bz = blockIdx.z;
    A += sA * bz; B += sB * bz;
    if (MODE == 2 || MODE == 3) rowsum += (long long)SEQ * bz;
    const int m0 = blockIdx.y * GBM;
    const int n0 = blockIdx.x * GBN;

    const int NITER = K / GBK;

    auto load_stage = [&](int c) {
        const int slot = c % GST;
        const uint32_t s_a = sbase + slot * STG_HALVES * 2;
        const uint32_t s_b = s_a + A_HALVES * 2;
        const long long koff = (long long)c * GBK;
        #pragma unroll
        for (int i = 0; i < 4; i++) {               // A: 1024 chunks of 16B
            int s = tid + i * 256;
            int row = s >> 3, ch = s & 7;
            cp_async16(s_a + (uint32_t)(row * SROW + ch * 8) * 2,
                       A + (long long)(m0 + row) * K + koff + ch * 8);
        }
        #pragma unroll
        for (int i = 0; i < 8; i++) {               // B: 2048 chunks of 16B
            int s = tid + i * 256;
            int row = s >> 3, ch = s & 7;
            cp_async16(s_b + (uint32_t)(row * SROW + ch * 8) * 2,
                       B + (long long)(n0 + row) * K + koff + ch * 8);
        }
        asm volatile("cp.async.commit_group;" ::: "memory");
    };

    float acc[4][8][4];
    #pragma unroll
    for (int mi = 0; mi < 4; mi++)
        #pragma unroll
        for (int ni = 0; ni < 8; ni++)
            #pragma unroll
            for (int r = 0; r < 4; r++) acc[mi][ni][r] = 0.f;

    load_stage(0);
    if (NITER > 1) load_stage(1);

    for (int it = 0; it < NITER; it++) {
        if (it < NITER - 1)
            asm volatile("cp.async.wait_group 1;" ::: "memory");
        else
            asm volatile("cp.async.wait_group 0;" ::: "memory");
        __syncthreads();

        if (it + 2 < NITER) load_stage(it + 2);

        const int slot = it % GST;
        const __half* as = smh + slot * STG_HALVES + wm0 * SROW;
        const __half* bs = smh + slot * STG_HALVES + A_HALVES + wn0 * SROW;

        #pragma unroll
        for (int kk = 0; kk < 4; kk++) {
            const int kc = kk * 16 + 4 * t;   // sigma16: {2t,2t+1,2t+8,2t+9} at 8B
            uint2 a2[4][2];
            #pragma unroll
            for (int mi = 0; mi < 4; mi++) {
                const __half* ap = as + (mi * 16 + g) * SROW + kc;
                a2[mi][0] = *(const uint2*)ap;                 // row g:   a0 | a2
                a2[mi][1] = *(const uint2*)(ap + 8 * SROW);    // row g+8: a1 | a3
            }
            uint2 b2[8];
            #pragma unroll
            for (int ni = 0; ni < 8; ni++)
                b2[ni] = *(const uint2*)(bs + (ni * 8 + g) * SROW + kc); // b0 | b1
            #pragma unroll
            for (int mi = 0; mi < 4; mi++)
                #pragma unroll
                for (int ni = 0; ni < 8; ni++)
                    mma_f16(acc[mi][ni],
                            a2[mi][0].x, a2[mi][1].x, a2[mi][0].y, a2[mi][1].y,
                            b2[ni].x, b2[ni].y);
        }
    }

    // ---------------- epilogue ----------------
    if (MODE == 3) {
        float* C = (float*)Cv + sC * bz;
        #pragma unroll
        for (int mi = 0; mi < 4; mi++) {
            const int row0 = m0 + wm0 + mi * 16 + g;
            const float i0 = 1.0f / rowsum[row0];
            const float i8 = 1.0f / rowsum[row0 + 8];
            #pragma unroll
            for (int ni = 0; ni < 8; ni++) {
                const int col = n0 + wn0 + ni * 8 + 2 * t;
                *(float2*)(C + (long long)row0 * ldc + col) =
                    make_float2(acc[mi][ni][0] * i0, acc[mi][ni][1] * i0);
                *(float2*)(C + (long long)(row0 + 8) * ldc + col) =
                    make_float2(acc[mi][ni][2] * i8, acc[mi][ni][3] * i8);
            }
        }
    } else if (MODE == 2) {
        __half* C = (__half*)Cv + sC * bz;
        #pragma unroll
        for (int mi = 0; mi < 4; mi++) {
            const int row0 = m0 + wm0 + mi * 16 + g;
            float s0 = 0.f, s8 = 0.f;
            #pragma unroll
            for (int ni = 0; ni < 8; ni++) {
                uint32_t u01 = pack2(__expf(alpha * acc[mi][ni][0]),
                                     __expf(alpha * acc[mi][ni][1]));
                uint32_t u23 = pack2(__expf(alpha * acc[mi][ni][2]),
                                     __expf(alpha * acc[mi][ni][3]));
                float2 f01 = unpack2(u01), f23 = unpack2(u23);
                s0 += f01.x + f01.y;  s8 += f23.x + f23.y;
                // sigma16 position of logical cols (2t, 2t+1):
                const int colm = n0 + wn0 + (ni >> 1) * 16 + 4 * t + 2 * (ni & 1);
                *(uint32_t*)(C + (long long)row0 * ldc + colm)       = u01;
                *(uint32_t*)(C + (long long)(row0 + 8) * ldc + colm) = u23;
            }
            s0 += __shfl_xor_sync(0xffffffffu, s0, 1);
            s0 += __shfl_xor_sync(0xffffffffu, s0, 2);
            s8 += __shfl_xor_sync(0xffffffffu, s8, 1);
            s8 += __shfl_xor_sync(0xffffffffu, s8, 2);
            if (t == 0) {
                atomicAdd(&rowsum[row0], s0);
                atomicAdd(&rowsum[row0 + 8], s8);
            }
        }
    } else if (MODE == 0) {
        __half* C = (__half*)Cv + sC * bz;
        #pragma unroll
        for (int mi = 0; mi < 4; mi++) {
            const int row0 = m0 + wm0 + mi * 16 + g;
            #pragma unroll
            for (int ni = 0; ni < 8; ni++) {
                const float2 bv = *(const float2*)(bias + n0 + wn0 + ni * 8 + 2 * t);
                uint32_t u01 = pack2(acc[mi][ni][0] + bv.x, acc[mi][ni][1] + bv.y);
                uint32_t u23 = pack2(acc[mi][ni][2] + bv.x, acc[mi][ni][3] + bv.y);
                const int colm = n0 + wn0 + (ni >> 1) * 16 + 4 * t + 2 * (ni & 1);
                *(uint32_t*)(C + (long long)row0 * ldc + colm)       = u01;
                *(uint32_t*)(C + (long long)(row0 + 8) * ldc + colm) = u23;
            }
        }
    } else {  // MODE 1: V, f32 natural
        float* C = (float*)Cv + sC * bz;
        #pragma unroll
        for (int mi = 0; mi < 4; mi++) {
            const int row0 = m0 + wm0 + mi * 16 + g;
            #pragma unroll
            for (int ni = 0; ni < 8; ni++) {
                const int col = n0 + wn0 + ni * 8 + 2 * t;
                const float2 bv = *(const float2*)(bias + col);
                *(float2*)(C + (long long)row0 * ldc + col) =
                    make_float2(acc[mi][ni][0] + bv.x, acc[mi][ni][1] + bv.y);
                *(float2*)(C + (long long)(row0 + 8) * ldc + col) =
                    make_float2(acc[mi][ni][2] + bv.x, acc[mi][ni][3] + bv.y);
            }
        }
    }
}

// ---------------------------------------------------------------------------
// x (f32) -> fp16 with sigma16 permutation per 16-group
// ---------------------------------------------------------------------------
__global__ __launch_bounds__(256)
void convert_sigma16(const float4* __restrict__ in, uint4* __restrict__ out, int n16)
{
    int i = blockIdx.x * 256 + threadIdx.x;
    if (i < n16) {
        float4 v0 = in[i * 4 + 0], v1 = in[i * 4 + 1];
        float4 v2 = in[i * 4 + 2], v3 = in[i * 4 + 3];
        // logical f0..f15 = v0.xyzw v1.xyzw v2.xyzw v3.xyzw
        uint4 o0, o1;
        o0.x = pack2(v0.x, v0.y);   // 0,1
        o0.y = pack2(v2.x, v2.y);   // 8,9
        o0.z = pack2(v0.z, v0.w);   // 2,3
        o0.w = pack2(v2.z, v2.w);   // 10,11
        o1.x = pack2(v1.x, v1.y);   // 4,5
        o1.y = pack2(v3.x, v3.y);   // 12,13
        o1.z = pack2(v1.z, v1.w);   // 6,7
        o1.w = pack2(v3.z, v3.w);   // 14,15
        out[i * 2]     = o0;
        out[i * 2 + 1] = o1;
    }
}

// ---------------------------------------------------------------------------
// Transpose f32 -> fp16 with sigma16 on the output-column (k) dim.
// in [R x Cc] f32, out [Cc x R] fp16: out[c][sig16(r)] = fp16(in[r][c])
// ---------------------------------------------------------------------------
__global__ __launch_bounds__(256)
void transpose_sigma16(const float* __restrict__ in, __half* __restrict__ out,
                       int R, int Cc, long long sIn, long long sOut)
{
    __shared__ float tbuf[32][33];
    const int bz = blockIdx.z;
    in += sIn * bz; out += sOut * bz;
    const int c0 = blockIdx.x * 32, r0 = blockIdx.y * 32;
    const int x = threadIdx.x, y = threadIdx.y;   // (32, 8)
    #pragma unroll
    for (int i = 0; i < 32; i += 8)
        tbuf[y + i][x] = in[(long long)(r0 + y + i) * Cc + c0 + x];
    __syncthreads();
    const int j = x & 15, jl = j & 7, hi = j >> 3;
    const int sx = (x & ~15) | ((jl >> 1) * 4 + hi * 2 + (jl & 1));
    #pragma unroll
    for (int i = 0; i < 32; i += 8)
        out[(long long)(c0 + y + i) * R + r0 + sx] = __float2half_rn(tbuf[x][y + i]);
}

__global__ __launch_bounds__(256)
void zero_kernel(float* __restrict__ p, int n)
{
    int i = blockIdx.x * 256 + threadIdx.x;
    if (i < n) p[i] = 0.f;
}

// ---------------------------------------------------------------------------
extern "C" void kernel_launch(void* const* d_in, const int* in_sizes, int n_in,
                              void* d_out, int out_size)
{
    const float* x  = (const float*)d_in[0];
    const float* Wq = (const float*)d_in[1];
    const float* bq = (const float*)d_in[2];
    const float* Wk = (const float*)d_in[3];
    const float* bk = (const float*)d_in[4];
    const float* Wv = (const float*)d_in[5];
    const float* bv = (const float*)d_in[6];
    float* out = (float*)d_out;

    __half *xc, *wqt, *wkt, *wvt, *q, *k, *vt, *p;
    float *v, *rs;
    cudaGetSymbolAddress((void**)&xc,  g_xc);
    cudaGetSymbolAddress((void**)&wqt, g_wqt);
    cudaGetSymbolAddress((void**)&wkt, g_wkt);
    cudaGetSymbolAddress((void**)&wvt, g_wvt);
    cudaGetSymbolAddress((void**)&q,   g_q);
    cudaGetSymbolAddress((void**)&k,   g_k);
    cudaGetSymbolAddress((void**)&v,   g_v);
    cudaGetSymbolAddress((void**)&vt,  g_vt);
    cudaGetSymbolAddress((void**)&p,   g_p);
    cudaGetSymbolAddress((void**)&rs,  g_rs);

    cudaFuncSetAttribute(gemm_mma<0>, cudaFuncAttributeMaxDynamicSharedMemorySize, GEMM_SMEM);
    cudaFuncSetAttribute(gemm_mma<1>, cudaFuncAttributeMaxDynamicSharedMemorySize, GEMM_SMEM);
    cudaFuncSetAttribute(gemm_mma<2>, cudaFuncAttributeMaxDynamicSharedMemorySize, GEMM_SMEM);
    cudaFuncSetAttribute(gemm_mma<3>, cudaFuncAttributeMaxDynamicSharedMemorySize, GEMM_SMEM);

    // 0) zero rowsums + convert x (fp16 + sigma16)
    zero_kernel<<<(BATCH * SEQ + 255) / 256, 256>>>(rs, BATCH * SEQ);
    convert_sigma16<<<(BATCH * SEQ * FEAT / 16 + 255) / 256, 256>>>(
        (const float4*)x, (uint4*)xc, BATCH * SEQ * FEAT / 16);

    // 1) W transposes (fp16 + sigma16 on f)
    dim3 tw(HID / 32, FEAT / 32, 1);
    transpose_sigma16<<<tw, dim3(32, 8)>>>(Wq, wqt, FEAT, HID, 0, 0);
    transpose_sigma16<<<tw, dim3(32, 8)>>>(Wk, wkt, FEAT, HID, 0, 0);
    transpose_sigma16<<<tw, dim3(32, 8)>>>(Wv, wvt, FEAT, HID, 0, 0);

    // 2) QKV projections
    dim3 gqkv(HID / GBN, (BATCH * SEQ) / GBM, 1);
    gemm_mma<0><<<gqkv, 256, GEMM_SMEM>>>(xc, wqt, bq, q, nullptr, FEAT, HID, 1.0f, 0, 0, 0);
    gemm_mma<0><<<gqkv, 256, GEMM_SMEM>>>(xc, wkt, bk, k, nullptr, FEAT, HID, 1.0f, 0, 0, 0);
    gemm_mma<1><<<gqkv, 256, GEMM_SMEM>>>(xc, wvt, bv, v, nullptr, FEAT, HID, 1.0f, 0, 0, 0);

    // 3) p = exp((Q K^T)/32) (fp16, sigma16-stored) + rowsums
    dim3 gs(SEQ / GBN, SEQ / GBM, BATCH);
    gemm_mma<2><<<gs, 256, GEMM_SMEM>>>(q, k, nullptr, p, rs, HID, SEQ, 1.0f / 32.0f,
                                        (long long)SEQ * HID, (long long)SEQ * HID,
                                        (long long)SEQ * SEQ);

    // 4) V^T (fp16 + sigma16 on s)
    dim3 tv(HID / 32, SEQ / 32, BATCH);
    transpose_sigma16<<<tv, dim3(32, 8)>>>(v, vt, SEQ, HID,
                                           (long long)SEQ * HID, (long long)HID * SEQ);

    // 5) out = (P V) / rowsum
    dim3 go(HID / GBN, SEQ / GBM, BATCH);
    gemm_mma<3><<<go, 256, GEMM_SMEM>>>(p, vt, nullptr, out, rs, SEQ, HID, 1.0f,
                                        (long long)SEQ * SEQ, (long long)HID * SEQ,
                                        (long long)SEQ * HID);
}

// round 9
// speedup vs baseline: 2.0478x; 1.0583x over previous
#include <cuda_runtime.h>
#include <cuda_fp16.h>
#include <cstdint>
#include <math.h>

#define BATCH 4
#define SEQ   4096
#define FEAT  1024
#define HID   1024

// ---------------------------------------------------------------------------
// Scratch (device globals). All fp16 MMA operands stored sigma16-permuted
// within 16-k-groups: mem order [0,1,8,9, 2,3,10,11, 4,5,12,13, 6,7,14,15]
// ---------------------------------------------------------------------------
__device__ __half g_xc [BATCH * SEQ * FEAT];   // x   (fp16, sig-f)   32 MB
__device__ __half g_wqt[FEAT * HID];           // Wq^T (fp16, sig-f)   2 MB
__device__ __half g_wkt[FEAT * HID];           // Wk^T (fp16, sig-f)   2 MB
__device__ __half g_wvt[FEAT * HID];           // Wv^T (fp16, sig-f)   2 MB
__device__ __half g_q  [BATCH * SEQ * HID];    // Q (fp16, sig-h)     32 MB
__device__ __half g_k  [BATCH * SEQ * HID];    // K (fp16, sig-h)     32 MB
__device__ float  g_v  [BATCH * SEQ * HID];    // V (f32 natural)     64 MB
__device__ __half g_vt [BATCH * HID * SEQ];    // V^T (fp16, sig-s)   32 MB
__device__ __half g_p  [(size_t)BATCH * SEQ * SEQ]; // exp(scores)   128 MB
__device__ float  g_rs [BATCH * SEQ];          // row sums of exp

// ---------------------------------------------------------------------------
__device__ __forceinline__ uint32_t pack2(float lo, float hi) {
    __half2 h = __floats2half2_rn(lo, hi);
    return *reinterpret_cast<uint32_t*>(&h);
}
__device__ __forceinline__ float2 unpack2(uint32_t u) {
    __half2 h = *reinterpret_cast<__half2*>(&u);
    return __half22float2(h);
}

__device__ __forceinline__ void cp_async16(uint32_t s, const void* g) {
    asm volatile("cp.async.cg.shared.global [%0], [%1], 16;"
                 :: "r"(s), "l"(__cvta_generic_to_global(g)) : "memory");
}

__device__ __forceinline__ uint32_t smem_u32(const void* p) {
    uint32_t a;
    asm("{ .reg .u64 t; cvta.to.shared.u64 t, %1; cvt.u32.u64 %0, t; }"
        : "=r"(a) : "l"(p));
    return a;
}

__device__ __forceinline__ void mma_f16(float* c, uint32_t a0, uint32_t a1,
                                        uint32_t a2, uint32_t a3,
                                        uint32_t b0, uint32_t b1) {
    asm volatile(
        "mma.sync.aligned.m16n8k16.row.col.f32.f16.f16.f32 "
        "{%0,%1,%2,%3}, {%4,%5,%6,%7}, {%8,%9}, {%0,%1,%2,%3};"
        : "+f"(c[0]), "+f"(c[1]), "+f"(c[2]), "+f"(c[3])
        : "r"(a0), "r"(a1), "r"(a2), "r"(a3), "r"(b0), "r"(b1));
}

// ---------------------------------------------------------------------------
// fp16 mma.sync GEMM (NT), sigma16-k layout, XOR-swizzled smem (128B rows).
//   store: 16B chunk ch of row r -> chunk (ch ^ (2*(r&3)))
//   read : fragment slot (4kk+t) of row r -> halves 16*(kk ^ (r&3)) + 4t
// (all fragment rows are == g (mod 4), so (r&3) == (g&3) at read time)
// Bank-conflict-free in all LDS/STS phases.
// BM=128, BN=256, BK=64 halves, 3 stages, 256 threads (8 warps 2x4 -> 64x64).
// Epilogue MODE: 0 = bias + fp16 + sigma16-store (Q/K)
//               1 = bias + f32 natural store (V)
//               2 = exp(alpha*acc) -> fp16 sigma16-store + rowsum (probs)
//               3 = acc / rowsum, f32 natural store (output)
// ---------------------------------------------------------------------------
#define GBM 128
#define GBN 256
#define GBK 64                                  // halves per k-iter
#define GST 3
#define SROW 64                                 // halves per smem row (128B exact)
#define A_HALVES (GBM * SROW)                   // 8192
#define B_HALVES (GBN * SROW)                   // 16384
#define STG_HALVES (A_HALVES + B_HALVES)        // 24576
#define GEMM_SMEM (GST * STG_HALVES * 2)        // 147456 bytes

template <int MODE>
__global__ __launch_bounds__(256, 1)
void gemm_mma(const __half* __restrict__ A, const __half* __restrict__ B,
              const float* __restrict__ bias, void* __restrict__ Cv,
              float* __restrict__ rowsum,
              int K, int ldc, float alpha,
              long long sA, long long sB, long long sC)
{
    extern __shared__ __half smh[];
    const uint32_t sbase = smem_u32(smh);

    const int tid = threadIdx.x;
    const int wid = tid >> 5, lane = tid & 31;
    const int g = lane >> 2, t = lane & 3;
    const int wm = wid >> 2, wn = wid & 3;
    const int wm0 = wm * 64, wn0 = wn * 64;

    const int bz = blockIdx.z;
    A += sA * bz; B += sB * bz;
    if (MODE == 2 || MODE == 3) rowsum += (long long)SEQ * bz;
    const int m0 = blockIdx.y * GBM;
    const int n0 = blockIdx.x * GBN;

    const int NITER = K / GBK;

    auto load_stage = [&](int c) {
        const int slot = c % GST;
        const uint32_t s_a = sbase + slot * STG_HALVES * 2;
        const uint32_t s_b = s_a + A_HALVES * 2;
        const long long koff = (long long)c * GBK;
        #pragma unroll
        for (int i = 0; i < 4; i++) {               // A: 1024 chunks of 16B
            int s = tid + i * 256;
            int row = s >> 3, ch = s & 7;
            int chs = ch ^ (2 * (row & 3));          // XOR swizzle
            cp_async16(s_a + (uint32_t)(row * 128 + chs * 16),
                       A + (long long)(m0 + row) * K + koff + ch * 8);
        }
        #pragma unroll
        for (int i = 0; i < 8; i++) {               // B: 2048 chunks of 16B
            int s = tid + i * 256;
            int row = s >> 3, ch = s & 7;
            int chs = ch ^ (2 * (row & 3));
            cp_async16(s_b + (uint32_t)(row * 128 + chs * 16),
                       B + (long long)(n0 + row) * K + koff + ch * 8);
        }
        asm volatile("cp.async.commit_group;" ::: "memory");
    };

    float acc[4][8][4];
    #pragma unroll
    for (int mi = 0; mi < 4; mi++)
        #pragma unroll
        for (int ni = 0; ni < 8; ni++)
            #pragma unroll
            for (int r = 0; r < 4; r++) acc[mi][ni][r] = 0.f;

    load_stage(0);
    if (NITER > 1) load_stage(1);

    for (int it = 0; it < NITER; it++) {
        if (it < NITER - 1)
            asm volatile("cp.async.wait_group 1;" ::: "memory");
        else
            asm volatile("cp.async.wait_group 0;" ::: "memory");
        __syncthreads();

        if (it + 2 < NITER) load_stage(it + 2);

        const int slot = it % GST;
        const __half* as = smh + slot * STG_HALVES + wm0 * SROW;
        const __half* bs = smh + slot * STG_HALVES + A_HALVES + wn0 * SROW;

        #pragma unroll
        for (int kk = 0; kk < 4; kk++) {
            // swizzled fragment offset (halves) within a row == g (mod 4):
            const int fo = 16 * (kk ^ (g & 3)) + 4 * t;
            uint2 a2[4][2];
            #pragma unroll
            for (int mi = 0; mi < 4; mi++) {
                const __half* ap = as + (mi * 16 + g) * SROW + fo;
                a2[mi][0] = *(const uint2*)ap;                 // row g:   a0 | a2
                a2[mi][1] = *(const uint2*)(ap + 8 * SROW);    // row g+8: a1 | a3
            }
            uint2 b2[8];
            #pragma unroll
            for (int ni = 0; ni < 8; ni++)
                b2[ni] = *(const uint2*)(bs + (ni * 8 + g) * SROW + fo); // b0 | b1
            #pragma unroll
            for (int mi = 0; mi < 4; mi++)
                #pragma unroll
                for (int ni = 0; ni < 8; ni++)
                    mma_f16(acc[mi][ni],
                            a2[mi][0].x, a2[mi][1].x, a2[mi][0].y, a2[mi][1].y,
                            b2[ni].x, b2[ni].y);
        }
    }

    // ---------------- epilogue ----------------
    if (MODE == 3) {
        float* C = (float*)Cv + sC * bz;
        #pragma unroll
        for (int mi = 0; mi < 4; mi++) {
            const int row0 = m0 + wm0 + mi * 16 + g;
            const float i0 = 1.0f / rowsum[row0];
            const float i8 = 1.0f / rowsum[row0 + 8];
            #pragma unroll
            for (int ni = 0; ni < 8; ni++) {
                const int col = n0 + wn0 + ni * 8 + 2 * t;
                *(float2*)(C + (long long)row0 * ldc + col) =
                    make_float2(acc[mi][ni][0] * i0, acc[mi][ni][1] * i0);
                *(float2*)(C + (long long)(row0 + 8) * ldc + col) =
                    make_float2(acc[mi][ni][2] * i8, acc[mi][ni][3] * i8);
            }
        }
    } else if (MODE == 2) {
        __half* C = (__half*)Cv + sC * bz;
        #pragma unroll
        for (int mi = 0; mi < 4; mi++) {
            const int row0 = m0 + wm0 + mi * 16 + g;
            float s0 = 0.f, s8 = 0.f;
            #pragma unroll
            for (int ni = 0; ni < 8; ni++) {
                uint32_t u01 = pack2(__expf(alpha * acc[mi][ni][0]),
                                     __expf(alpha * acc[mi][ni][1]));
                uint32_t u23 = pack2(__expf(alpha * acc[mi][ni][2]),
                                     __expf(alpha * acc[mi][ni][3]));
                float2 f01 = unpack2(u01), f23 = unpack2(u23);
                s0 += f01.x + f01.y;  s8 += f23.x + f23.y;
                // sigma16 position of logical cols (2t, 2t+1):
                const int colm = n0 + wn0 + (ni >> 1) * 16 + 4 * t + 2 * (ni & 1);
                *(uint32_t*)(C + (long long)row0 * ldc + colm)       = u01;
                *(uint32_t*)(C + (long long)(row0 + 8) * ldc + colm) = u23;
            }
            s0 += __shfl_xor_sync(0xffffffffu, s0, 1);
            s0 += __shfl_xor_sync(0xffffffffu, s0, 2);
            s8 += __shfl_xor_sync(0xffffffffu, s8, 1);
            s8 += __shfl_xor_sync(0xffffffffu, s8, 2);
            if (t == 0) {
                atomicAdd(&rowsum[row0], s0);
                atomicAdd(&rowsum[row0 + 8], s8);
            }
        }
    } else if (MODE == 0) {
        __half* C = (__half*)Cv + sC * bz;
        #pragma unroll
        for (int mi = 0; mi < 4; mi++) {
            const int row0 = m0 + wm0 + mi * 16 + g;
            #pragma unroll
            for (int ni = 0; ni < 8; ni++) {
                const float2 bv = *(const float2*)(bias + n0 + wn0 + ni * 8 + 2 * t);
                uint32_t u01 = pack2(acc[mi][ni][0] + bv.x, acc[mi][ni][1] + bv.y);
                uint32_t u23 = pack2(acc[mi][ni][2] + bv.x, acc[mi][ni][3] + bv.y);
                const int colm = n0 + wn0 + (ni >> 1) * 16 + 4 * t + 2 * (ni & 1);
                *(uint32_t*)(C + (long long)row0 * ldc + colm)       = u01;
                *(uint32_t*)(C + (long long)(row0 + 8) * ldc + colm) = u23;
            }
        }
    } else {  // MODE 1: V, f32 natural
        float* C = (float*)Cv + sC * bz;
        #pragma unroll
        for (int mi = 0; mi < 4; mi++) {
            const int row0 = m0 + wm0 + mi * 16 + g;
            #pragma unroll
            for (int ni = 0; ni < 8; ni++) {
                const int col = n0 + wn0 + ni * 8 + 2 * t;
                const float2 bv = *(const float2*)(bias + col);
                *(float2*)(C + (long long)row0 * ldc + col) =
                    make_float2(acc[mi][ni][0] + bv.x, acc[mi][ni][1] + bv.y);
                *(float2*)(C + (long long)(row0 + 8) * ldc + col) =
                    make_float2(acc[mi][ni][2] + bv.x, acc[mi][ni][3] + bv.y);
            }
        }
    }
}

// ---------------------------------------------------------------------------
// x (f32) -> fp16 with sigma16 permutation per 16-group
// ---------------------------------------------------------------------------
__global__ __launch_bounds__(256)
void convert_sigma16(const float4* __restrict__ in, uint4* __restrict__ out, int n16)
{
    int i = blockIdx.x * 256 + threadIdx.x;
    if (i < n16) {
        float4 v0 = in[i * 4 + 0], v1 = in[i * 4 + 1];
        float4 v2 = in[i * 4 + 2], v3 = in[i * 4 + 3];
        // logical f0..f15 = v0.xyzw v1.xyzw v2.xyzw v3.xyzw
        uint4 o0, o1;
        o0.x = pack2(v0.x, v0.y);   // 0,1
        o0.y = pack2(v2.x, v2.y);   // 8,9
        o0.z = pack2(v0.z, v0.w);   // 2,3
        o0.w = pack2(v2.z, v2.w);   // 10,11
        o1.x = pack2(v1.x, v1.y);   // 4,5
        o1.y = pack2(v3.x, v3.y);   // 12,13
        o1.z = pack2(v1.z, v1.w);   // 6,7
        o1.w = pack2(v3.z, v3.w);   // 14,15
        out[i * 2]     = o0;
        out[i * 2 + 1] = o1;
    }
}

// ---------------------------------------------------------------------------
// Transpose f32 -> fp16 with sigma16 on the output-column (k) dim.
// in [R x Cc] f32, out [Cc x R] fp16: out[c][sig16(r)] = fp16(in[r][c])
// ---------------------------------------------------------------------------
__global__ __launch_bounds__(256)
void transpose_sigma16(const float* __restrict__ in, __half* __restrict__ out,
                       int R, int Cc, long long sIn, long long sOut)
{
    __shared__ float tbuf[32][33];
    const int bz = blockIdx.z;
    in += sIn * bz; out += sOut * bz;
    const int c0 = blockIdx.x * 32, r0 = blockIdx.y * 32;
    const int x = threadIdx.x, y = threadIdx.y;   // (32, 8)
    #pragma unroll
    for (int i = 0; i < 32; i += 8)
        tbuf[y + i][x] = in[(long long)(r0 + y + i) * Cc + c0 + x];
    __syncthreads();
    const int j = x & 15, jl = j & 7, hi = j >> 3;
    const int sx = (x & ~15) | ((jl >> 1) * 4 + hi * 2 + (jl & 1));
    #pragma unroll
    for (int i = 0; i < 32; i += 8)
        out[(long long)(c0 + y + i) * R + r0 + sx] = __float2half_rn(tbuf[x][y + i]);
}

__global__ __launch_bounds__(256)
void zero_kernel(float* __restrict__ p, int n)
{
    int i = blockIdx.x * 256 + threadIdx.x;
    if (i < n) p[i] = 0.f;
}

// ---------------------------------------------------------------------------
extern "C" void kernel_launch(void* const* d_in, const int* in_sizes, int n_in,
                              void* d_out, int out_size)
{
    const float* x  = (const float*)d_in[0];
    const float* Wq = (const float*)d_in[1];
    const float* bq = (const float*)d_in[2];
    const float* Wk = (const float*)d_in[3];
    const float* bk = (const float*)d_in[4];
    const float* Wv = (const float*)d_in[5];
    const float* bv = (const float*)d_in[6];
    float* out = (float*)d_out;

    __half *xc, *wqt, *wkt, *wvt, *q, *k, *vt, *p;
    float *v, *rs;
    cudaGetSymbolAddress((void**)&xc,  g_xc);
    cudaGetSymbolAddress((void**)&wqt, g_wqt);
    cudaGetSymbolAddress((void**)&wkt, g_wkt);
    cudaGetSymbolAddress((void**)&wvt, g_wvt);
    cudaGetSymbolAddress((void**)&q,   g_q);
    cudaGetSymbolAddress((void**)&k,   g_k);
    cudaGetSymbolAddress((void**)&v,   g_v);
    cudaGetSymbolAddress((void**)&vt,  g_vt);
    cudaGetSymbolAddress((void**)&p,   g_p);
    cudaGetSymbolAddress((void**)&rs,  g_rs);

    cudaFuncSetAttribute(gemm_mma<0>, cudaFuncAttributeMaxDynamicSharedMemorySize, GEMM_SMEM);
    cudaFuncSetAttribute(gemm_mma<1>, cudaFuncAttributeMaxDynamicSharedMemorySize, GEMM_SMEM);
    cudaFuncSetAttribute(gemm_mma<2>, cudaFuncAttributeMaxDynamicSharedMemorySize, GEMM_SMEM);
    cudaFuncSetAttribute(gemm_mma<3>, cudaFuncAttributeMaxDynamicSharedMemorySize, GEMM_SMEM);

    // 0) zero rowsums + convert x (fp16 + sigma16)
    zero_kernel<<<(BATCH * SEQ + 255) / 256, 256>>>(rs, BATCH * SEQ);
    convert_sigma16<<<(BATCH * SEQ * FEAT / 16 + 255) / 256, 256>>>(
        (const float4*)x, (uint4*)xc, BATCH * SEQ * FEAT / 16);

    // 1) W transposes (fp16 + sigma16 on f)
    dim3 tw(HID / 32, FEAT / 32, 1);
    transpose_sigma16<<<tw, dim3(32, 8)>>>(Wq, wqt, FEAT, HID, 0, 0);
    transpose_sigma16<<<tw, dim3(32, 8)>>>(Wk, wkt, FEAT, HID, 0, 0);
    transpose_sigma16<<<tw, dim3(32, 8)>>>(Wv, wvt, FEAT, HID, 0, 0);

    // 2) QKV projections
    dim3 gqkv(HID / GBN, (BATCH * SEQ) / GBM, 1);
    gemm_mma<0><<<gqkv, 256, GEMM_SMEM>>>(xc, wqt, bq, q, nullptr, FEAT, HID, 1.0f, 0, 0, 0);
    gemm_mma<0><<<gqkv, 256, GEMM_SMEM>>>(xc, wkt, bk, k, nullptr, FEAT, HID, 1.0f, 0, 0, 0);
    gemm_mma<1><<<gqkv, 256, GEMM_SMEM>>>(xc, wvt, bv, v, nullptr, FEAT, HID, 1.0f, 0, 0, 0);

    // 3) p = exp((Q K^T)/32) (fp16, sigma16-stored) + rowsums
    dim3 gs(SEQ / GBN, SEQ / GBM, BATCH);
    gemm_mma<2><<<gs, 256, GEMM_SMEM>>>(q, k, nullptr, p, rs, HID, SEQ, 1.0f / 32.0f,
                                        (long long)SEQ * HID, (long long)SEQ * HID,
                                        (long long)SEQ * SEQ);

    // 4) V^T (fp16 + sigma16 on s)
    dim3 tv(HID / 32, SEQ / 32, BATCH);
    transpose_sigma16<<<tv, dim3(32, 8)>>>(v, vt, SEQ, HID,
                                           (long long)SEQ * HID, (long long)HID * SEQ);

    // 5) out = (P V) / rowsum
    dim3 go(HID / GBN, SEQ / GBM, BATCH);
    gemm_mma<3><<<go, 256, GEMM_SMEM>>>(p, vt, nullptr, out, rs, SEQ, HID, 1.0f,
                                        (long long)SEQ * SEQ, (long long)HID * SEQ,
                                        (long long)SEQ * HID);
}

// round 12
// speedup vs baseline: 2.1636x; 1.0565x over previous
#include <cuda_runtime.h>
#include <cuda_fp16.h>
#include <cstdint>
#include <math.h>

#define BATCH 4
#define SEQ   4096
#define FEAT  1024
#define HID   1024

// ---------------------------------------------------------------------------
// Scratch (device globals). All fp16 MMA operands stored sigma16-permuted
// within 16-k-groups: mem order [0,1,8,9, 2,3,10,11, 4,5,12,13, 6,7,14,15]
// ---------------------------------------------------------------------------
__device__ __half g_xc [BATCH * SEQ * FEAT];   // x   (fp16, sig-f)   32 MB
__device__ __half g_wqt[FEAT * HID];           // Wq^T (fp16, sig-f)   2 MB
__device__ __half g_wkt[FEAT * HID];           // Wk^T (fp16, sig-f)   2 MB
__device__ __half g_wvt[FEAT * HID];           // Wv^T (fp16, sig-f)   2 MB
__device__ __half g_q  [BATCH * SEQ * HID];    // Q (fp16, sig-h)     32 MB
__device__ __half g_k  [BATCH * SEQ * HID];    // K (fp16, sig-h)     32 MB
__device__ __half g_vt [BATCH * HID * SEQ];    // V^T (fp16, sig-s)   32 MB
__device__ __half g_p  [(size_t)BATCH * SEQ * SEQ]; // exp(scores)   128 MB
__device__ float  g_rs [BATCH * SEQ];          // row sums of exp

// ---------------------------------------------------------------------------
__device__ __forceinline__ uint32_t pack2(float lo, float hi) {
    __half2 h = __floats2half2_rn(lo, hi);
    return *reinterpret_cast<uint32_t*>(&h);
}
__device__ __forceinline__ float2 unpack2(uint32_t u) {
    __half2 h = *reinterpret_cast<__half2*>(&u);
    return __half22float2(h);
}

__device__ __forceinline__ void cp_async16(uint32_t s, const void* g) {
    asm volatile("cp.async.cg.shared.global [%0], [%1], 16;"
                 :: "r"(s), "l"(__cvta_generic_to_global(g)) : "memory");
}

__device__ __forceinline__ uint32_t smem_u32(const void* p) {
    uint32_t a;
    asm("{ .reg .u64 t; cvta.to.shared.u64 t, %1; cvt.u32.u64 %0, t; }"
        : "=r"(a) : "l"(p));
    return a;
}

// sigma16 position of logical index s within its 16-group
__device__ __forceinline__ int sig16pos(int s) {
    int q = s & 15;
    return (s & ~15) | (4 * ((q & 7) >> 1) + 2 * (q >> 3) + (q & 1));
}

__device__ __forceinline__ void mma_f16(float* c, uint32_t a0, uint32_t a1,
                                        uint32_t a2, uint32_t a3,
                                        uint32_t b0, uint32_t b1) {
    asm volatile(
        "mma.sync.aligned.m16n8k16.row.col.f32.f16.f16.f32 "
        "{%0,%1,%2,%3}, {%4,%5,%6,%7}, {%8,%9}, {%0,%1,%2,%3};"
        : "+f"(c[0]), "+f"(c[1]), "+f"(c[2]), "+f"(c[3])
        : "r"(a0), "r"(a1), "r"(a2), "r"(a3), "r"(b0), "r"(b1));
}

// ---------------------------------------------------------------------------
// Shared tile geometry. BM=128, BN=256, BK=64 halves, 3 stages, 256 threads
// (8 warps 2x4 -> 64x64 per warp). XOR-swizzled smem (128B rows):
//   store: 16B chunk ch of row r -> chunk (ch ^ (2*(r&3)))
//   read : fragment slot (4kk+t) of row r -> halves 16*(kk ^ (r&3)) + 4t
// ---------------------------------------------------------------------------
#define GBM 128
#define GBN 256
#define GBK 64
#define GST 3
#define SROW 64
#define A_HALVES (GBM * SROW)                   // 8192
#define B_HALVES (GBN * SROW)                   // 16384
#define STG_HALVES (A_HALVES + B_HALVES)        // 24576
#define GEMM_SMEM (GST * STG_HALVES * 2)        // 147456 bytes

// Mainloop: computes acc for tile (m0, n0) of A x B^T.
#define GEMM_MAINLOOP(A_, B_, K_)                                              \
    const int NITER = (K_) / GBK;                                              \
    auto load_stage = [&](int c) {                                             \
        const int slot = c % GST;                                              \
        const uint32_t s_a = sbase + slot * STG_HALVES * 2;                    \
        const uint32_t s_b = s_a + A_HALVES * 2;                               \
        const long long koff = (long long)c * GBK;                             \
        _Pragma("unroll")                                                      \
        for (int i = 0; i < 4; i++) {                                          \
            int s = tid + i * 256;                                             \
            int row = s >> 3, ch = s & 7;                                      \
            int chs = ch ^ (2 * (row & 3));                                    \
            cp_async16(s_a + (uint32_t)(row * 128 + chs * 16),                 \
                       (A_) + (long long)(m0 + row) * (K_) + koff + ch * 8);   \
        }                                                                      \
        _Pragma("unroll")                                                      \
        for (int i = 0; i < 8; i++) {                                          \
            int s = tid + i * 256;                                             \
            int row = s >> 3, ch = s & 7;                                      \
            int chs = ch ^ (2 * (row & 3));                                    \
            cp_async16(s_b + (uint32_t)(row * 128 + chs * 16),                 \
                       (B_) + (long long)(n0 + row) * (K_) + koff + ch * 8);   \
        }                                                                      \
        asm volatile("cp.async.commit_group;" ::: "memory");                   \
    };                                                                         \
    load_stage(0);                                                             \
    if (NITER > 1) load_stage(1);                                              \
    for (int it = 0; it < NITER; it++) {                                       \
        if (it < NITER - 1)                                                    \
            asm volatile("cp.async.wait_group 1;" ::: "memory");               \
        else                                                                   \
            asm volatile("cp.async.wait_group 0;" ::: "memory");               \
        __syncthreads();                                                       \
        if (it + 2 < NITER) load_stage(it + 2);                                \
        const int slot = it % GST;                                             \
        const __half* as = smh + slot * STG_HALVES + wm0 * SROW;               \
        const __half* bs = smh + slot * STG_HALVES + A_HALVES + wn0 * SROW;    \
        _Pragma("unroll")                                                      \
        for (int kk = 0; kk < 4; kk++) {                                       \
            const int fo = 16 * (kk ^ (g & 3)) + 4 * t;                        \
            uint2 a2[4][2];                                                    \
            _Pragma("unroll")                                                  \
            for (int mi = 0; mi < 4; mi++) {                                   \
                const __half* ap = as + (mi * 16 + g) * SROW + fo;             \
                a2[mi][0] = *(const uint2*)ap;                                 \
                a2[mi][1] = *(const uint2*)(ap + 8 * SROW);                    \
            }                                                                  \
            uint2 b2[8];                                                       \
            _Pragma("unroll")                                                  \
            for (int ni = 0; ni < 8; ni++)                                     \
                b2[ni] = *(const uint2*)(bs + (ni * 8 + g) * SROW + fo);       \
            _Pragma("unroll")                                                  \
            for (int mi = 0; mi < 4; mi++)                                     \
                _Pragma("unroll")                                              \
                for (int ni = 0; ni < 8; ni++)                                 \
                    mma_f16(acc[mi][ni],                                       \
                            a2[mi][0].x, a2[mi][1].x, a2[mi][0].y, a2[mi][1].y,\
                            b2[ni].x, b2[ni].y);                               \
        }                                                                      \
    }

// ---------------------------------------------------------------------------
// Merged QKV projection: grid.z selects (Wq,bq,q) / (Wk,bk,k) / (Wv,bv,vt).
// z<2: fp16 + sigma16 store. z==2: transposed store (V^T, sigma16 on s)
// staged through smem with coalesced 256B row write-out.
// ---------------------------------------------------------------------------
__global__ __launch_bounds__(256, 1)
void qkv_gemm(const __half* __restrict__ A,
              const __half* __restrict__ Bq, const __half* __restrict__ Bk,
              const __half* __restrict__ Bv,
              const float* __restrict__ bq_, const float* __restrict__ bk_,
              const float* __restrict__ bv_,
              __half* __restrict__ q, __half* __restrict__ k,
              __half* __restrict__ vt)
{
    extern __shared__ __half smh[];
    const uint32_t sbase = smem_u32(smh);

    const int tid = threadIdx.x;
    const int wid = tid >> 5, lane = tid & 31;
    const int g = lane >> 2, t = lane & 3;
    const int wm = wid >> 2, wn = wid & 3;
    const int wm0 = wm * 64, wn0 = wn * 64;

    const int z = blockIdx.z;
    const __half* B    = (z == 0) ? Bq  : (z == 1) ? Bk  : Bv;
    const float*  bias = (z == 0) ? bq_ : (z == 1) ? bk_ : bv_;

    const int m0 = blockIdx.y * GBM;
    const int n0 = blockIdx.x * GBN;

    float acc[4][8][4];
    #pragma unroll
    for (int mi = 0; mi < 4; mi++)
        #pragma unroll
        for (int ni = 0; ni < 8; ni++)
            #pragma unroll
            for (int r = 0; r < 4; r++) acc[mi][ni][r] = 0.f;

    GEMM_MAINLOOP(A, B, FEAT)

    if (z < 2) {
        __half* C = (z == 0) ? q : k;
        #pragma unroll
        for (int mi = 0; mi < 4; mi++) {
            const int row0 = m0 + wm0 + mi * 16 + g;
            #pragma unroll
            for (int ni = 0; ni < 8; ni++) {
                const float2 bv2 = *(const float2*)(bias + n0 + wn0 + ni * 8 + 2 * t);
                uint32_t u01 = pack2(acc[mi][ni][0] + bv2.x, acc[mi][ni][1] + bv2.y);
                uint32_t u23 = pack2(acc[mi][ni][2] + bv2.x, acc[mi][ni][3] + bv2.y);
                const int colm = n0 + wn0 + (ni >> 1) * 16 + 4 * t + 2 * (ni & 1);
                *(uint32_t*)(C + (long long)row0 * HID + colm)       = u01;
                *(uint32_t*)(C + (long long)(row0 + 8) * HID + colm) = u23;
            }
        }
    } else {
        // ---- V: transpose-in-smem epilogue, write V^T (sigma16 on s) ----
        const int TSTR = 136;                        // padded row stride (halves)
        __syncthreads();                             // mainloop smem reads done
        #pragma unroll
        for (int mi = 0; mi < 4; mi++) {
            const int s0 = wm0 + mi * 16 + g;
            const int sp0 = sig16pos(s0), sp8 = sig16pos(s0 + 8);
            #pragma unroll
            for (int ni = 0; ni < 8; ni++) {
                const int h0 = wn0 + ni * 8 + 2 * t;
                const float2 bv2 = *(const float2*)(bias + n0 + h0);
                smh[h0 * TSTR + sp0]       = __float2half_rn(acc[mi][ni][0] + bv2.x);
                smh[(h0 + 1) * TSTR + sp0] = __float2half_rn(acc[mi][ni][1] + bv2.y);
                smh[h0 * TSTR + sp8]       = __float2half_rn(acc[mi][ni][2] + bv2.x);
                smh[(h0 + 1) * TSTR + sp8] = __float2half_rn(acc[mi][ni][3] + bv2.y);
            }
        }
        __syncthreads();
        const int bzb = m0 >> 12;                    // batch index
        const int sg  = m0 & 4095;                   // s offset within batch
        __half* vtb = vt + (size_t)bzb * HID * SEQ + sg;
        const int hh  = lane >> 4;                   // half-warp row select
        const int off = lane & 15;                   // 16B chunk within row
        #pragma unroll
        for (int r = 0; r < 32; r += 2) {
            const int h = wid * 32 + r + hh;
            uint4 val = *(uint4*)(smh + h * TSTR + off * 8);
            *(uint4*)(vtb + (size_t)(n0 + h) * SEQ + off * 8) = val;
        }
    }
}

// ---------------------------------------------------------------------------
// Attention GEMMs. MODE 2 = exp(alpha*acc) -> fp16 sigma16-store + rowsum.
//                  MODE 3 = acc / rowsum, f32 natural store.
// ---------------------------------------------------------------------------
template <int MODE>
__global__ __launch_bounds__(256, 1)
void gemm_mma(const __half* __restrict__ A, const __half* __restrict__ B,
              void* __restrict__ Cv, float* __restrict__ rowsum,
              int K, int ldc, float alpha,
              long long sA, long long sB, long long sC)
{
    extern __shared__ __half smh[];
    const uint32_t sbase = smem_u32(smh);

    const int tid = threadIdx.x;
    const int wid = tid >> 5, lane = tid & 31;
    const int g = lane >> 2, t = lane & 3;
    const int wm = wid >> 2, wn = wid & 3;
    const int wm0 = wm * 64, wn0 = wn * 64;

    const int bz = blockIdx.z;
    A += sA * bz; B += sB * bz;
    rowsum += (long long)SEQ * bz;
    const int m0 = blockIdx.y * GBM;
    const int n0 = blockIdx.x * GBN;

    float acc[4][8][4];
    #pragma unroll
    for (int mi = 0; mi < 4; mi++)
        #pragma unroll
        for (int ni = 0; ni < 8; ni++)
            #pragma unroll
            for (int r = 0; r < 4; r++) acc[mi][ni][r] = 0.f;

    GEMM_MAINLOOP(A, B, K)

    if (MODE == 3) {
        float* C = (float*)Cv + sC * bz;
        #pragma unroll
        for (int mi = 0; mi < 4; mi++) {
            const int row0 = m0 + wm0 + mi * 16 + g;
            const float i0 = 1.0f / rowsum[row0];
            const float i8 = 1.0f / rowsum[row0 + 8];
            #pragma unroll
            for (int ni = 0; ni < 8; ni++) {
                const int col = n0 + wn0 + ni * 8 + 2 * t;
                *(float2*)(C + (long long)row0 * ldc + col) =
                    make_float2(acc[mi][ni][0] * i0, acc[mi][ni][1] * i0);
                *(float2*)(C + (long long)(row0 + 8) * ldc + col) =
                    make_float2(acc[mi][ni][2] * i8, acc[mi][ni][3] * i8);
            }
        }
    } else {
        __half* C = (__half*)Cv + sC * bz;
        #pragma unroll
        for (int mi = 0; mi < 4; mi++) {
            const int row0 = m0 + wm0 + mi * 16 + g;
            float s0 = 0.f, s8 = 0.f;
            #pragma unroll
            for (int ni = 0; ni < 8; ni++) {
                uint32_t u01 = pack2(__expf(alpha * acc[mi][ni][0]),
                                     __expf(alpha * acc[mi][ni][1]));
                uint32_t u23 = pack2(__expf(alpha * acc[mi][ni][2]),
                                     __expf(alpha * acc[mi][ni][3]));
                float2 f01 = unpack2(u01), f23 = unpack2(u23);
                s0 += f01.x + f01.y;  s8 += f23.x + f23.y;
                const int colm = n0 + wn0 + (ni >> 1) * 16 + 4 * t + 2 * (ni & 1);
                *(uint32_t*)(C + (long long)row0 * ldc + colm)       = u01;
                *(uint32_t*)(C + (long long)(row0 + 8) * ldc + colm) = u23;
            }
            s0 += __shfl_xor_sync(0xffffffffu, s0, 1);
            s0 += __shfl_xor_sync(0xffffffffu, s0, 2);
            s8 += __shfl_xor_sync(0xffffffffu, s8, 1);
            s8 += __shfl_xor_sync(0xffffffffu, s8, 2);
            if (t == 0) {
                atomicAdd(&rowsum[row0], s0);
                atomicAdd(&rowsum[row0 + 8], s8);
            }
        }
    }
}

// ---------------------------------------------------------------------------
// x (f32) -> fp16 with sigma16 permutation per 16-group
// ---------------------------------------------------------------------------
__global__ __launch_bounds__(256)
void convert_sigma16(const float4* __restrict__ in, uint4* __restrict__ out, int n16)
{
    int i = blockIdx.x * 256 + threadIdx.x;
    if (i < n16) {
        float4 v0 = in[i * 4 + 0], v1 = in[i * 4 + 1];
        float4 v2 = in[i * 4 + 2], v3 = in[i * 4 + 3];
        uint4 o0, o1;
        o0.x = pack2(v0.x, v0.y);   // 0,1
        o0.y = pack2(v2.x, v2.y);   // 8,9
        o0.z = pack2(v0.z, v0.w);   // 2,3
        o0.w = pack2(v2.z, v2.w);   // 10,11
        o1.x = pack2(v1.x, v1.y);   // 4,5
        o1.y = pack2(v3.x, v3.y);   // 12,13
        o1.z = pack2(v1.z, v1.w);   // 6,7
        o1.w = pack2(v3.z, v3.w);   // 14,15
        out[i * 2]     = o0;
        out[i * 2 + 1] = o1;
    }
}

// ---------------------------------------------------------------------------
// Transpose f32 -> fp16 with sigma16 on the output-column (k) dim (weights).
// ---------------------------------------------------------------------------
__global__ __launch_bounds__(256)
void transpose_sigma16(const float* __restrict__ in, __half* __restrict__ out,
                       int R, int Cc)
{
    __shared__ float tbuf[32][33];
    const int c0 = blockIdx.x * 32, r0 = blockIdx.y * 32;
    const int x = threadIdx.x, y = threadIdx.y;   // (32, 8)
    #pragma unroll
    for (int i = 0; i < 32; i += 8)
        tbuf[y + i][x] = in[(long long)(r0 + y + i) * Cc + c0 + x];
    __syncthreads();
    const int sx = sig16pos(x);
    #pragma unroll
    for (int i = 0; i < 32; i += 8)
        out[(long long)(c0 + y + i) * R + r0 + sx] = __float2half_rn(tbuf[x][y + i]);
}

__global__ __launch_bounds__(256)
void zero_kernel(float* __restrict__ p, int n)
{
    int i = blockIdx.x * 256 + threadIdx.x;
    if (i < n) p[i] = 0.f;
}

// ---------------------------------------------------------------------------
extern "C" void kernel_launch(void* const* d_in, const int* in_sizes, int n_in,
                              void* d_out, int out_size)
{
    const float* x  = (const float*)d_in[0];
    const float* Wq = (const float*)d_in[1];
    const float* bq = (const float*)d_in[2];
    const float* Wk = (const float*)d_in[3];
    const float* bk = (const float*)d_in[4];
    const float* Wv = (const float*)d_in[5];
    const float* bv = (const float*)d_in[6];
    float* out = (float*)d_out;

    __half *xc, *wqt, *wkt, *wvt, *q, *k, *vt, *p;
    float *rs;
    cudaGetSymbolAddress((void**)&xc,  g_xc);
    cudaGetSymbolAddress((void**)&wqt, g_wqt);
    cudaGetSymbolAddress((void**)&wkt, g_wkt);
    cudaGetSymbolAddress((void**)&wvt, g_wvt);
    cudaGetSymbolAddress((void**)&q,   g_q);
    cudaGetSymbolAddress((void**)&k,   g_k);
    cudaGetSymbolAddress((void**)&vt,  g_vt);
    cudaGetSymbolAddress((void**)&p,   g_p);
    cudaGetSymbolAddress((void**)&rs,  g_rs);

    cudaFuncSetAttribute(qkv_gemm,    cudaFuncAttributeMaxDynamicSharedMemorySize, GEMM_SMEM);
    cudaFuncSetAttribute(gemm_mma<2>, cudaFuncAttributeMaxDynamicSharedMemorySize, GEMM_SMEM);
    cudaFuncSetAttribute(gemm_mma<3>, cudaFuncAttributeMaxDynamicSharedMemorySize, GEMM_SMEM);

    // 0) zero rowsums + convert x (fp16 + sigma16)
    zero_kernel<<<(BATCH * SEQ + 255) / 256, 256>>>(rs, BATCH * SEQ);
    convert_sigma16<<<(BATCH * SEQ * FEAT / 16 + 255) / 256, 256>>>(
        (const float4*)x, (uint4*)xc, BATCH * SEQ * FEAT / 16);

    // 1) W transposes (fp16 + sigma16 on f)
    dim3 tw(HID / 32, FEAT / 32, 1);
    transpose_sigma16<<<tw, dim3(32, 8)>>>(Wq, wqt, FEAT, HID);
    transpose_sigma16<<<tw, dim3(32, 8)>>>(Wk, wkt, FEAT, HID);
    transpose_sigma16<<<tw, dim3(32, 8)>>>(Wv, wvt, FEAT, HID);

    // 2) Merged QKV projections (z: 0=Q, 1=K, 2=V->V^T)
    dim3 gqkv(HID / GBN, (BATCH * SEQ) / GBM, 3);
    qkv_gemm<<<gqkv, 256, GEMM_SMEM>>>(xc, wqt, wkt, wvt, bq, bk, bv, q, k, vt);

    // 3) p = exp((Q K^T)/32) (fp16, sigma16-stored) + rowsums
    dim3 gs(SEQ / GBN, SEQ / GBM, BATCH);
    gemm_mma<2><<<gs, 256, GEMM_SMEM>>>(q, k, p, rs, HID, SEQ, 1.0f / 32.0f,
                                        (long long)SEQ * HID, (long long)SEQ * HID,
                                        (long long)SEQ * SEQ);

    // 4) out = (P V) / rowsum
    dim3 go(HID / GBN, SEQ / GBM, BATCH);
    gemm_mma<3><<<go, 256, GEMM_SMEM>>>(p, vt, out, rs, SEQ, HID, 1.0f,
                                        (long long)SEQ * SEQ, (long long)HID * SEQ,
                                        (long long)SEQ * HID);
}

// round 15
// speedup vs baseline: 2.1765x; 1.0060x over previous
#include <cuda_runtime.h>
#include <cuda_fp16.h>
#include <cstdint>
#include <math.h>

#define BATCH 4
#define SEQ   4096
#define FEAT  1024
#define HID   1024

// ---------------------------------------------------------------------------
// Scratch (device globals). All fp16 MMA operands stored sigma16-permuted
// within 16-k-groups: mem order [0,1,8,9, 2,3,10,11, 4,5,12,13, 6,7,14,15]
// ---------------------------------------------------------------------------
__device__ __half g_xc [BATCH * SEQ * FEAT];   // x   (fp16, sig-f)   32 MB
__device__ __half g_wqt[FEAT * HID];           // Wq^T (fp16, sig-f)   2 MB
__device__ __half g_wkt[FEAT * HID];           // Wk^T (fp16, sig-f)   2 MB
__device__ __half g_wvt[FEAT * HID];           // Wv^T (fp16, sig-f)   2 MB
__device__ __half g_q  [BATCH * SEQ * HID];    // Q (fp16, sig-h)     32 MB
__device__ __half g_k  [BATCH * SEQ * HID];    // K (fp16, sig-h)     32 MB
__device__ __half g_vt [BATCH * HID * SEQ];    // V^T (fp16, sig-s)   32 MB
__device__ __half g_p  [(size_t)BATCH * SEQ * SEQ]; // exp(scores)   128 MB
__device__ float  g_rs [BATCH * SEQ];          // row sums of exp

// ---------------------------------------------------------------------------
__device__ __forceinline__ uint32_t pack2(float lo, float hi) {
    __half2 h = __floats2half2_rn(lo, hi);
    return *reinterpret_cast<uint32_t*>(&h);
}
__device__ __forceinline__ float2 unpack2(uint32_t u) {
    __half2 h = *reinterpret_cast<__half2*>(&u);
    return __half22float2(h);
}

__device__ __forceinline__ void cp_async16(uint32_t s, const void* g) {
    asm volatile("cp.async.cg.shared.global [%0], [%1], 16;"
                 :: "r"(s), "l"(__cvta_generic_to_global(g)) : "memory");
}

__device__ __forceinline__ uint32_t smem_u32(const void* p) {
    uint32_t a;
    asm("{ .reg .u64 t; cvta.to.shared.u64 t, %1; cvt.u32.u64 %0, t; }"
        : "=r"(a) : "l"(p));
    return a;
}

// sigma16 position of logical index s within its 16-group
__device__ __forceinline__ int sig16pos(int s) {
    int q = s & 15;
    return (s & ~15) | (4 * ((q & 7) >> 1) + 2 * (q >> 3) + (q & 1));
}

__device__ __forceinline__ void mma_f16(float* c, uint32_t a0, uint32_t a1,
                                        uint32_t a2, uint32_t a3,
                                        uint32_t b0, uint32_t b1) {
    asm volatile(
        "mma.sync.aligned.m16n8k16.row.col.f32.f16.f16.f32 "
        "{%0,%1,%2,%3}, {%4,%5,%6,%7}, {%8,%9}, {%0,%1,%2,%3};"
        : "+f"(c[0]), "+f"(c[1]), "+f"(c[2]), "+f"(c[3])
        : "r"(a0), "r"(a1), "r"(a2), "r"(a3), "r"(b0), "r"(b1));
}

// ---------------------------------------------------------------------------
// Tile geometry. BM=128, BN=NI*32 (NI=8 or 4), BK=64 halves, 3 stages,
// 256 threads (8 warps 2x4 -> 64 x NI*8 per warp). XOR-swizzled smem:
//   store: 16B chunk ch of row r -> chunk (ch ^ (2*(r&3)))
//   read : fragment slot (4kk+t) of row r -> halves 16*(kk ^ (r&3)) + 4t
// ---------------------------------------------------------------------------
#define GBM 128
#define GBK 64
#define GST 3
#define SROW 64
#define A_HALVES (GBM * SROW)                   // 8192
#define SMEM_FOR(NI) (GST * (A_HALVES + (NI) * 32 * SROW) * 2)

// Mainloop: computes acc[4][NI_][4] for tile (m0, n0) of A x B^T.
#define GEMM_MAINLOOP(A_, B_, K_, NI_)                                         \
    constexpr int BHALVES_ = (NI_) * 32 * SROW;                                \
    constexpr int STGH_ = A_HALVES + BHALVES_;                                 \
    const int NITER = (K_) / GBK;                                              \
    auto load_stage = [&](int c) {                                             \
        const int slot = c % GST;                                              \
        const uint32_t s_a = sbase + slot * STGH_ * 2;                         \
        const uint32_t s_b = s_a + A_HALVES * 2;                               \
        const long long koff = (long long)c * GBK;                             \
        _Pragma("unroll")                                                      \
        for (int i = 0; i < 4; i++) {                                          \
            int s = tid + i * 256;                                             \
            int row = s >> 3, ch = s & 7;                                      \
            int chs = ch ^ (2 * (row & 3));                                    \
            cp_async16(s_a + (uint32_t)(row * 128 + chs * 16),                 \
                       (A_) + (long long)(m0 + row) * (K_) + koff + ch * 8);   \
        }                                                                      \
        _Pragma("unroll")                                                      \
        for (int i = 0; i < (NI_); i++) {                                      \
            int s = tid + i * 256;                                             \
            int row = s >> 3, ch = s & 7;                                      \
            int chs = ch ^ (2 * (row & 3));                                    \
            cp_async16(s_b + (uint32_t)(row * 128 + chs * 16),                 \
                       (B_) + (long long)(n0 + row) * (K_) + koff + ch * 8);   \
        }                                                                      \
        asm volatile("cp.async.commit_group;" ::: "memory");                   \
    };                                                                         \
    load_stage(0);                                                             \
    if (NITER > 1) load_stage(1);                                              \
    for (int it = 0; it < NITER; it++) {                                       \
        if (it < NITER - 1)                                                    \
            asm volatile("cp.async.wait_group 1;" ::: "memory");               \
        else                                                                   \
            asm volatile("cp.async.wait_group 0;" ::: "memory");               \
        __syncthreads();                                                       \
        if (it + 2 < NITER) load_stage(it + 2);                                \
        const int slot = it % GST;                                             \
        const __half* as = smh + slot * STGH_ + wm0 * SROW;                    \
        const __half* bs = smh + slot * STGH_ + A_HALVES + wn0 * SROW;         \
        _Pragma("unroll")                                                      \
        for (int kk = 0; kk < 4; kk++) {                                       \
            const int fo = 16 * (kk ^ (g & 3)) + 4 * t;                        \
            uint2 a2[4][2];                                                    \
            _Pragma("unroll")                                                  \
            for (int mi = 0; mi < 4; mi++) {                                   \
                const __half* ap = as + (mi * 16 + g) * SROW + fo;             \
                a2[mi][0] = *(const uint2*)ap;                                 \
                a2[mi][1] = *(const uint2*)(ap + 8 * SROW);                    \
            }                                                                  \
            uint2 b2[NI_];                                                     \
            _Pragma("unroll")                                                  \
            for (int ni = 0; ni < (NI_); ni++)                                 \
                b2[ni] = *(const uint2*)(bs + (ni * 8 + g) * SROW + fo);       \
            _Pragma("unroll")                                                  \
            for (int mi = 0; mi < 4; mi++)                                     \
                _Pragma("unroll")                                              \
                for (int ni = 0; ni < (NI_); ni++)                             \
                    mma_f16(acc[mi][ni],                                       \
                            a2[mi][0].x, a2[mi][1].x, a2[mi][0].y, a2[mi][1].y,\
                            b2[ni].x, b2[ni].y);                               \
        }                                                                      \
    }

// ---------------------------------------------------------------------------
// Merged QKV projection (NI=8): grid.z selects Q / K / V->V^T.
// z<2: fp16 + sigma16 store. z==2: transposed store (V^T, sigma16 on s)
// staged through smem with coalesced 256B row write-out.
// ---------------------------------------------------------------------------
__global__ __launch_bounds__(256, 1)
void qkv_gemm(const __half* __restrict__ A,
              const __half* __restrict__ Bq, const __half* __restrict__ Bk,
              const __half* __restrict__ Bv,
              const float* __restrict__ bq_, const float* __restrict__ bk_,
              const float* __restrict__ bv_,
              __half* __restrict__ q, __half* __restrict__ k,
              __half* __restrict__ vt)
{
    extern __shared__ __half smh[];
    const uint32_t sbase = smem_u32(smh);

    const int tid = threadIdx.x;
    const int wid = tid >> 5, lane = tid & 31;
    const int g = lane >> 2, t = lane & 3;
    const int wm = wid >> 2, wn = wid & 3;
    const int wm0 = wm * 64, wn0 = wn * 64;

    const int z = blockIdx.z;
    const __half* B    = (z == 0) ? Bq  : (z == 1) ? Bk  : Bv;
    const float*  bias = (z == 0) ? bq_ : (z == 1) ? bk_ : bv_;

    const int m0 = blockIdx.y * GBM;
    const int n0 = blockIdx.x * 256;

    float acc[4][8][4];
    #pragma unroll
    for (int mi = 0; mi < 4; mi++)
        #pragma unroll
        for (int ni = 0; ni < 8; ni++)
            #pragma unroll
            for (int r = 0; r < 4; r++) acc[mi][ni][r] = 0.f;

    GEMM_MAINLOOP(A, B, FEAT, 8)

    if (z < 2) {
        __half* C = (z == 0) ? q : k;
        #pragma unroll
        for (int mi = 0; mi < 4; mi++) {
            const int row0 = m0 + wm0 + mi * 16 + g;
            #pragma unroll
            for (int ni = 0; ni < 8; ni++) {
                const float2 bv2 = *(const float2*)(bias + n0 + wn0 + ni * 8 + 2 * t);
                uint32_t u01 = pack2(acc[mi][ni][0] + bv2.x, acc[mi][ni][1] + bv2.y);
                uint32_t u23 = pack2(acc[mi][ni][2] + bv2.x, acc[mi][ni][3] + bv2.y);
                const int colm = n0 + wn0 + (ni >> 1) * 16 + 4 * t + 2 * (ni & 1);
                *(uint32_t*)(C + (long long)row0 * HID + colm)       = u01;
                *(uint32_t*)(C + (long long)(row0 + 8) * HID + colm) = u23;
            }
        }
    } else {
        // ---- V: transpose-in-smem epilogue, write V^T (sigma16 on s) ----
        const int TSTR = 136;                        // padded row stride (halves)
        __syncthreads();                             // mainloop smem reads done
        #pragma unroll
        for (int mi = 0; mi < 4; mi++) {
            const int s0 = wm0 + mi * 16 + g;
            const int sp0 = sig16pos(s0), sp8 = sig16pos(s0 + 8);
            #pragma unroll
            for (int ni = 0; ni < 8; ni++) {
                const int h0 = wn0 + ni * 8 + 2 * t;
                const float2 bv2 = *(const float2*)(bias + n0 + h0);
                smh[h0 * TSTR + sp0]       = __float2half_rn(acc[mi][ni][0] + bv2.x);
                smh[(h0 + 1) * TSTR + sp0] = __float2half_rn(acc[mi][ni][1] + bv2.y);
                smh[h0 * TSTR + sp8]       = __float2half_rn(acc[mi][ni][2] + bv2.x);
                smh[(h0 + 1) * TSTR + sp8] = __float2half_rn(acc[mi][ni][3] + bv2.y);
            }
        }
        __syncthreads();
        const int bzb = m0 >> 12;                    // batch index
        const int sg  = m0 & 4095;                   // s offset within batch
        __half* vtb = vt + (size_t)bzb * HID * SEQ + sg;
        const int hh  = lane >> 4;                   // half-warp row select
        const int off = lane & 15;                   // 16B chunk within row
        #pragma unroll
        for (int r = 0; r < 32; r += 2) {
            const int h = wid * 32 + r + hh;
            uint4 val = *(uint4*)(smh + h * TSTR + off * 8);
            *(uint4*)(vtb + (size_t)(n0 + h) * SEQ + off * 8) = val;
        }
    }
}

// ---------------------------------------------------------------------------
// Attention GEMMs. MODE 2 (NI=8) = exp(alpha*acc) -> fp16 sigma16 + rowsum.
//                  MODE 3 (NI=4) = acc / rowsum, f32 natural store.
// ---------------------------------------------------------------------------
template <int MODE, int NI>
__global__ __launch_bounds__(256, 1)
void gemm_mma(const __half* __restrict__ A, const __half* __restrict__ B,
              void* __restrict__ Cv, float* __restrict__ rowsum,
              int K, int ldc, float alpha,
              long long sA, long long sB, long long sC)
{
    extern __shared__ __half smh[];
    const uint32_t sbase = smem_u32(smh);

    const int tid = threadIdx.x;
    const int wid = tid >> 5, lane = tid & 31;
    const int g = lane >> 2, t = lane & 3;
    const int wm = wid >> 2, wn = wid & 3;
    const int wm0 = wm * 64, wn0 = wn * (NI * 8);

    const int bz = blockIdx.z;
    A += sA * bz; B += sB * bz;
    rowsum += (long long)SEQ * bz;
    const int m0 = blockIdx.y * GBM;
    const int n0 = blockIdx.x * (NI * 32);

    float acc[4][NI][4];
    #pragma unroll
    for (int mi = 0; mi < 4; mi++)
        #pragma unroll
        for (int ni = 0; ni < NI; ni++)
            #pragma unroll
            for (int r = 0; r < 4; r++) acc[mi][ni][r] = 0.f;

    GEMM_MAINLOOP(A, B, K, NI)

    if (MODE == 3) {
        float* C = (float*)Cv + sC * bz;
        #pragma unroll
        for (int mi = 0; mi < 4; mi++) {
            const int row0 = m0 + wm0 + mi * 16 + g;
            const float i0 = 1.0f / rowsum[row0];
            const float i8 = 1.0f / rowsum[row0 + 8];
            #pragma unroll
            for (int ni = 0; ni < NI; ni++) {
                const int col = n0 + wn0 + ni * 8 + 2 * t;
                *(float2*)(C + (long long)row0 * ldc + col) =
                    make_float2(acc[mi][ni][0] * i0, acc[mi][ni][1] * i0);
                *(float2*)(C + (long long)(row0 + 8) * ldc + col) =
                    make_float2(acc[mi][ni][2] * i8, acc[mi][ni][3] * i8);
            }
        }
    } else {
        __half* C = (__half*)Cv + sC * bz;
        #pragma unroll
        for (int mi = 0; mi < 4; mi++) {
            const int row0 = m0 + wm0 + mi * 16 + g;
            float s0 = 0.f, s8 = 0.f;
            #pragma unroll
            for (int ni = 0; ni < NI; ni++) {
                uint32_t u01 = pack2(__expf(alpha * acc[mi][ni][0]),
                                     __expf(alpha * acc[mi][ni][1]));
                uint32_t u23 = pack2(__expf(alpha * acc[mi][ni][2]),
                                     __expf(alpha * acc[mi][ni][3]));
                float2 f01 = unpack2(u01), f23 = unpack2(u23);
                s0 += f01.x + f01.y;  s8 += f23.x + f23.y;
                const int colm = n0 + wn0 + (ni >> 1) * 16 + 4 * t + 2 * (ni & 1);
                *(uint32_t*)(C + (long long)row0 * ldc + colm)       = u01;
                *(uint32_t*)(C + (long long)(row0 + 8) * ldc + colm) = u23;
            }
            s0 += __shfl_xor_sync(0xffffffffu, s0, 1);
            s0 += __shfl_xor_sync(0xffffffffu, s0, 2);
            s8 += __shfl_xor_sync(0xffffffffu, s8, 1);
            s8 += __shfl_xor_sync(0xffffffffu, s8, 2);
            if (t == 0) {
                atomicAdd(&rowsum[row0], s0);
                atomicAdd(&rowsum[row0 + 8], s8);
            }
        }
    }
}

// ---------------------------------------------------------------------------
// x (f32) -> fp16 with sigma16 permutation per 16-group
// ---------------------------------------------------------------------------
__global__ __launch_bounds__(256)
void convert_sigma16(const float4* __restrict__ in, uint4* __restrict__ out, int n16)
{
    int i = blockIdx.x * 256 + threadIdx.x;
    if (i < n16) {
        float4 v0 = in[i * 4 + 0], v1 = in[i * 4 + 1];
        float4 v2 = in[i * 4 + 2], v3 = in[i * 4 + 3];
        uint4 o0, o1;
        o0.x = pack2(v0.x, v0.y);   // 0,1
        o0.y = pack2(v2.x, v2.y);   // 8,9
        o0.z = pack2(v0.z, v0.w);   // 2,3
        o0.w = pack2(v2.z, v2.w);   // 10,11
        o1.x = pack2(v1.x, v1.y);   // 4,5
        o1.y = pack2(v3.x, v3.y);   // 12,13
        o1.z = pack2(v1.z, v1.w);   // 6,7
        o1.w = pack2(v3.z, v3.w);   // 14,15
        out[i * 2]     = o0;
        out[i * 2 + 1] = o1;
    }
}

// ---------------------------------------------------------------------------
// Transpose f32 -> fp16 with sigma16 on the output-column (k) dim (weights).
// ---------------------------------------------------------------------------
__global__ __launch_bounds__(256)
void transpose_sigma16(const float* __restrict__ in, __half* __restrict__ out,
                       int R, int Cc)
{
    __shared__ float tbuf[32][33];
    const int c0 = blockIdx.x * 32, r0 = blockIdx.y * 32;
    const int x = threadIdx.x, y = threadIdx.y;   // (32, 8)
    #pragma unroll
    for (int i = 0; i < 32; i += 8)
        tbuf[y + i][x] = in[(long long)(r0 + y + i) * Cc + c0 + x];
    __syncthreads();
    const int sx = sig16pos(x);
    #pragma unroll
    for (int i = 0; i < 32; i += 8)
        out[(long long)(c0 + y + i) * R + r0 + sx] = __float2half_rn(tbuf[x][y + i]);
}

__global__ __launch_bounds__(256)
void zero_kernel(float* __restrict__ p, int n)
{
    int i = blockIdx.x * 256 + threadIdx.x;
    if (i < n) p[i] = 0.f;
}

// ---------------------------------------------------------------------------
extern "C" void kernel_launch(void* const* d_in, const int* in_sizes, int n_in,
                              void* d_out, int out_size)
{
    const float* x  = (const float*)d_in[0];
    const float* Wq = (const float*)d_in[1];
    const float* bq = (const float*)d_in[2];
    const float* Wk = (const float*)d_in[3];
    const float* bk = (const float*)d_in[4];
    const float* Wv = (const float*)d_in[5];
    const float* bv = (const float*)d_in[6];
    float* out = (float*)d_out;

    __half *xc, *wqt, *wkt, *wvt, *q, *k, *vt, *p;
    float *rs;
    cudaGetSymbolAddress((void**)&xc,  g_xc);
    cudaGetSymbolAddress((void**)&wqt, g_wqt);
    cudaGetSymbolAddress((void**)&wkt, g_wkt);
    cudaGetSymbolAddress((void**)&wvt, g_wvt);
    cudaGetSymbolAddress((void**)&q,   g_q);
    cudaGetSymbolAddress((void**)&k,   g_k);
    cudaGetSymbolAddress((void**)&vt,  g_vt);
    cudaGetSymbolAddress((void**)&p,   g_p);
    cudaGetSymbolAddress((void**)&rs,  g_rs);

    cudaFuncSetAttribute(qkv_gemm,
                         cudaFuncAttributeMaxDynamicSharedMemorySize, SMEM_FOR(8));
    cudaFuncSetAttribute(gemm_mma<2, 8>,
                         cudaFuncAttributeMaxDynamicSharedMemorySize, SMEM_FOR(8));
    cudaFuncSetAttribute(gemm_mma<3, 4>,
                         cudaFuncAttributeMaxDynamicSharedMemorySize, SMEM_FOR(4));

    // 0) zero rowsums + convert x (fp16 + sigma16)
    zero_kernel<<<(BATCH * SEQ + 255) / 256, 256>>>(rs, BATCH * SEQ);
    convert_sigma16<<<(BATCH * SEQ * FEAT / 16 + 255) / 256, 256>>>(
        (const float4*)x, (uint4*)xc, BATCH * SEQ * FEAT / 16);

    // 1) W transposes (fp16 + sigma16 on f)
    dim3 tw(HID / 32, FEAT / 32, 1);
    transpose_sigma16<<<tw, dim3(32, 8)>>>(Wq, wqt, FEAT, HID);
    transpose_sigma16<<<tw, dim3(32, 8)>>>(Wk, wkt, FEAT, HID);
    transpose_sigma16<<<tw, dim3(32, 8)>>>(Wv, wvt, FEAT, HID);

    // 2) Merged QKV projections (z: 0=Q, 1=K, 2=V->V^T), BN=256
    dim3 gqkv(HID / 256, (BATCH * SEQ) / GBM, 3);
    qkv_gemm<<<gqkv, 256, SMEM_FOR(8)>>>(xc, wqt, wkt, wvt, bq, bk, bv, q, k, vt);

    // 3) p = exp((Q K^T)/32) (fp16, sigma16-stored) + rowsums, BN=256
    dim3 gs(SEQ / 256, SEQ / GBM, BATCH);
    gemm_mma<2, 8><<<gs, 256, SMEM_FOR(8)>>>(q, k, p, rs, HID, SEQ, 1.0f / 32.0f,
                                             (long long)SEQ * HID,
                                             (long long)SEQ * HID,
                                             (long long)SEQ * SEQ);

    // 4) out = (P V) / rowsum, BN=128 (1024 CTAs -> ~7 waves, small tail)
    dim3 go(HID / 128, SEQ / GBM, BATCH);
    gemm_mma<3, 4><<<go, 256, SMEM_FOR(4)>>>(p, vt, out, rs, SEQ, HID, 1.0f,
                                             (long long)SEQ * SEQ,
                                             (long long)HID * SEQ,
                                             (long long)SEQ * HID);
}

// round 16
// speedup vs baseline: 2.2957x; 1.0548x over previous
#include <cuda_runtime.h>
#include <cuda_fp16.h>
#include <cstdint>
#include <math.h>

#define BATCH 4
#define SEQ   4096
#define FEAT  1024
#define HID   1024

// ---------------------------------------------------------------------------
// Scratch (device globals). All fp16 MMA operands stored sigma16-permuted
// within 16-k-groups: mem order [0,1,8,9, 2,3,10,11, 4,5,12,13, 6,7,14,15]
// ---------------------------------------------------------------------------
__device__ __half g_xc [BATCH * SEQ * FEAT];   // x   (fp16, sig-f)   32 MB
__device__ __half g_wqt[FEAT * HID];           // Wq^T (fp16, sig-f)   2 MB
__device__ __half g_wkt[FEAT * HID];           // Wk^T (fp16, sig-f)   2 MB
__device__ __half g_wvt[FEAT * HID];           // Wv^T (fp16, sig-f)   2 MB
__device__ __half g_q  [BATCH * SEQ * HID];    // Q (fp16, sig-h)     32 MB
__device__ __half g_k  [BATCH * SEQ * HID];    // K (fp16, sig-h)     32 MB
__device__ __half g_vt [BATCH * HID * SEQ];    // V^T (fp16, sig-s)   32 MB
__device__ __half g_p  [(size_t)BATCH * SEQ * SEQ]; // exp(scores)   128 MB
__device__ float  g_rs [BATCH * SEQ];          // row sums of exp

// ---------------------------------------------------------------------------
__device__ __forceinline__ uint32_t pack2(float lo, float hi) {
    __half2 h = __floats2half2_rn(lo, hi);
    return *reinterpret_cast<uint32_t*>(&h);
}
__device__ __forceinline__ float2 unpack2(uint32_t u) {
    __half2 h = *reinterpret_cast<__half2*>(&u);
    return __half22float2(h);
}

__device__ __forceinline__ void cp_async16(uint32_t s, const void* g) {
    asm volatile("cp.async.cg.shared.global [%0], [%1], 16;"
                 :: "r"(s), "l"(__cvta_generic_to_global(g)) : "memory");
}

__device__ __forceinline__ uint32_t smem_u32(const void* p) {
    uint32_t a;
    asm("{ .reg .u64 t; cvta.to.shared.u64 t, %1; cvt.u32.u64 %0, t; }"
        : "=r"(a) : "l"(p));
    return a;
}

// sigma16 position of logical index s within its 16-group
__device__ __forceinline__ int sig16pos(int s) {
    int q = s & 15;
    return (s & ~15) | (4 * ((q & 7) >> 1) + 2 * (q >> 3) + (q & 1));
}

__device__ __forceinline__ void mma_f16(float* c, uint32_t a0, uint32_t a1,
                                        uint32_t a2, uint32_t a3,
                                        uint32_t b0, uint32_t b1) {
    asm volatile(
        "mma.sync.aligned.m16n8k16.row.col.f32.f16.f16.f32 "
        "{%0,%1,%2,%3}, {%4,%5,%6,%7}, {%8,%9}, {%0,%1,%2,%3};"
        : "+f"(c[0]), "+f"(c[1]), "+f"(c[2]), "+f"(c[3])
        : "r"(a0), "r"(a1), "r"(a2), "r"(a3), "r"(b0), "r"(b1));
}

// ---------------------------------------------------------------------------
// Tile geometry. BM=128, BN=NI*32 (NI=8 or 4), BK=64 halves, 3 stages,
// 256 threads (8 warps 2x4 -> 64 x NI*8 per warp). XOR-swizzled smem:
//   store: 16B chunk ch of row r -> chunk (ch ^ (2*(r&3)))
//   read : fragment slot (4kk+t) of row r -> halves 16*(kk ^ (r&3)) + 4t
// ---------------------------------------------------------------------------
#define GBM 128
#define GBK 64
#define GST 3
#define SROW 64
#define A_HALVES (GBM * SROW)                   // 8192
#define SMEM_FOR(NI) (GST * (A_HALVES + (NI) * 32 * SROW) * 2)

// Mainloop: computes acc[4][NI_][4] for tile (m0, n0) of A x B^T.
#define GEMM_MAINLOOP(A_, B_, K_, NI_)                                         \
    constexpr int BHALVES_ = (NI_) * 32 * SROW;                                \
    constexpr int STGH_ = A_HALVES + BHALVES_;                                 \
    const int NITER = (K_) / GBK;                                              \
    auto load_stage = [&](int c) {                                             \
        const int slot = c % GST;                                              \
        const uint32_t s_a = sbase + slot * STGH_ * 2;                         \
        const uint32_t s_b = s_a + A_HALVES * 2;                               \
        const long long koff = (long long)c * GBK;                             \
        _Pragma("unroll")                                                      \
        for (int i = 0; i < 4; i++) {                                          \
            int s = tid + i * 256;                                             \
            int row = s >> 3, ch = s & 7;                                      \
            int chs = ch ^ (2 * (row & 3));                                    \
            cp_async16(s_a + (uint32_t)(row * 128 + chs * 16),                 \
                       (A_) + (long long)(m0 + row) * (K_) + koff + ch * 8);   \
        }                                                                      \
        _Pragma("unroll")                                                      \
        for (int i = 0; i < (NI_); i++) {                                      \
            int s = tid + i * 256;                                             \
            int row = s >> 3, ch = s & 7;                                      \
            int chs = ch ^ (2 * (row & 3));                                    \
            cp_async16(s_b + (uint32_t)(row * 128 + chs * 16),                 \
                       (B_) + (long long)(n0 + row) * (K_) + koff + ch * 8);   \
        }                                                                      \
        asm volatile("cp.async.commit_group;" ::: "memory");                   \
    };                                                                         \
    load_stage(0);                                                             \
    if (NITER > 1) load_stage(1);                                              \
    for (int it = 0; it < NITER; it++) {                                       \
        if (it < NITER - 1)                                                    \
            asm volatile("cp.async.wait_group 1;" ::: "memory");               \
        else                                                                   \
            asm volatile("cp.async.wait_group 0;" ::: "memory");               \
        __syncthreads();                                                       \
        if (it + 2 < NITER) load_stage(it + 2);                                \
        const int slot = it % GST;                                             \
        const __half* as = smh + slot * STGH_ + wm0 * SROW;                    \
        const __half* bs = smh + slot * STGH_ + A_HALVES + wn0 * SROW;         \
        _Pragma("unroll")                                                      \
        for (int kk = 0; kk < 4; kk++) {                                       \
            const int fo = 16 * (kk ^ (g & 3)) + 4 * t;                        \
            uint2 a2[4][2];                                                    \
            _Pragma("unroll")                                                  \
            for (int mi = 0; mi < 4; mi++) {                                   \
                const __half* ap = as + (mi * 16 + g) * SROW + fo;             \
                a2[mi][0] = *(const uint2*)ap;                                 \
                a2[mi][1] = *(const uint2*)(ap + 8 * SROW);                    \
            }                                                                  \
            uint2 b2[NI_];                                                     \
            _Pragma("unroll")                                                  \
            for (int ni = 0; ni < (NI_); ni++)                                 \
                b2[ni] = *(const uint2*)(bs + (ni * 8 + g) * SROW + fo);       \
            _Pragma("unroll")                                                  \
            for (int mi = 0; mi < 4; mi++)                                     \
                _Pragma("unroll")                                              \
                for (int ni = 0; ni < (NI_); ni++)                             \
                    mma_f16(acc[mi][ni],                                       \
                            a2[mi][0].x, a2[mi][1].x, a2[mi][0].y, a2[mi][1].y,\
                            b2[ni].x, b2[ni].y);                               \
        }                                                                      \
    }

// ---------------------------------------------------------------------------
// Merged QKV projection (NI=8): grid.z selects Q / K / V->V^T.
// z<2: fp16 + sigma16 store. z==2: transposed store (V^T, sigma16 on s)
// staged through smem with coalesced 256B row write-out.
// ---------------------------------------------------------------------------
__global__ __launch_bounds__(256, 1)
void qkv_gemm(const __half* __restrict__ A,
              const __half* __restrict__ Bq, const __half* __restrict__ Bk,
              const __half* __restrict__ Bv,
              const float* __restrict__ bq_, const float* __restrict__ bk_,
              const float* __restrict__ bv_,
              __half* __restrict__ q, __half* __restrict__ k,
              __half* __restrict__ vt)
{
    extern __shared__ __half smh[];
    const uint32_t sbase = smem_u32(smh);

    const int tid = threadIdx.x;
    const int wid = tid >> 5, lane = tid & 31;
    const int g = lane >> 2, t = lane & 3;
    const int wm = wid >> 2, wn = wid & 3;
    const int wm0 = wm * 64, wn0 = wn * 64;

    const int z = blockIdx.z;
    const __half* B    = (z == 0) ? Bq  : (z == 1) ? Bk  : Bv;
    const float*  bias = (z == 0) ? bq_ : (z == 1) ? bk_ : bv_;

    const int m0 = blockIdx.y * GBM;
    const int n0 = blockIdx.x * 256;

    float acc[4][8][4];
    #pragma unroll
    for (int mi = 0; mi < 4; mi++)
        #pragma unroll
        for (int ni = 0; ni < 8; ni++)
            #pragma unroll
            for (int r = 0; r < 4; r++) acc[mi][ni][r] = 0.f;

    GEMM_MAINLOOP(A, B, FEAT, 8)

    if (z < 2) {
        __half* C = (z == 0) ? q : k;
        #pragma unroll
        for (int mi = 0; mi < 4; mi++) {
            const int row0 = m0 + wm0 + mi * 16 + g;
            #pragma unroll
            for (int ni = 0; ni < 8; ni++) {
                const float2 bv2 = *(const float2*)(bias + n0 + wn0 + ni * 8 + 2 * t);
                uint32_t u01 = pack2(acc[mi][ni][0] + bv2.x, acc[mi][ni][1] + bv2.y);
                uint32_t u23 = pack2(acc[mi][ni][2] + bv2.x, acc[mi][ni][3] + bv2.y);
                const int colm = n0 + wn0 + (ni >> 1) * 16 + 4 * t + 2 * (ni & 1);
                *(uint32_t*)(C + (long long)row0 * HID + colm)       = u01;
                *(uint32_t*)(C + (long long)(row0 + 8) * HID + colm) = u23;
            }
        }
    } else {
        // ---- V: transpose-in-smem epilogue, write V^T (sigma16 on s) ----
        const int TSTR = 136;                        // padded row stride (halves)
        __syncthreads();                             // mainloop smem reads done
        #pragma unroll
        for (int mi = 0; mi < 4; mi++) {
            const int s0 = wm0 + mi * 16 + g;
            const int sp0 = sig16pos(s0), sp8 = sig16pos(s0 + 8);
            #pragma unroll
            for (int ni = 0; ni < 8; ni++) {
                const int h0 = wn0 + ni * 8 + 2 * t;
                const float2 bv2 = *(const float2*)(bias + n0 + h0);
                smh[h0 * TSTR + sp0]       = __float2half_rn(acc[mi][ni][0] + bv2.x);
                smh[(h0 + 1) * TSTR + sp0] = __float2half_rn(acc[mi][ni][1] + bv2.y);
                smh[h0 * TSTR + sp8]       = __float2half_rn(acc[mi][ni][2] + bv2.x);
                smh[(h0 + 1) * TSTR + sp8] = __float2half_rn(acc[mi][ni][3] + bv2.y);
            }
        }
        __syncthreads();
        const int bzb = m0 >> 12;                    // batch index
        const int sg  = m0 & 4095;                   // s offset within batch
        __half* vtb = vt + (size_t)bzb * HID * SEQ + sg;
        const int hh  = lane >> 4;                   // half-warp row select
        const int off = lane & 15;                   // 16B chunk within row
        #pragma unroll
        for (int r = 0; r < 32; r += 2) {
            const int h = wid * 32 + r + hh;
            uint4 val = *(uint4*)(smh + h * TSTR + off * 8);
            *(uint4*)(vtb + (size_t)(n0 + h) * SEQ + off * 8) = val;
        }
    }
}

// ---------------------------------------------------------------------------
// Attention GEMMs. MODE 2 (NI=8) = exp(alpha*acc) -> fp16 sigma16 + rowsum.
//                  MODE 3 (NI=4) = acc / rowsum, f32 natural store.
// MODE 3 runs 2 CTAs/SM (96 KB smem each) for better latency hiding.
// ---------------------------------------------------------------------------
template <int MODE, int NI>
__global__ __launch_bounds__(256, (MODE == 3) ? 2 : 1)
void gemm_mma(const __half* __restrict__ A, const __half* __restrict__ B,
              void* __restrict__ Cv, float* __restrict__ rowsum,
              int K, int ldc, float alpha,
              long long sA, long long sB, long long sC)
{
    extern __shared__ __half smh[];
    const uint32_t sbase = smem_u32(smh);

    const int tid = threadIdx.x;
    const int wid = tid >> 5, lane = tid & 31;
    const int g = lane >> 2, t = lane & 3;
    const int wm = wid >> 2, wn = wid & 3;
    const int wm0 = wm * 64, wn0 = wn * (NI * 8);

    const int bz = blockIdx.z;
    A += sA * bz; B += sB * bz;
    rowsum += (long long)SEQ * bz;
    const int m0 = blockIdx.y * GBM;
    const int n0 = blockIdx.x * (NI * 32);

    float acc[4][NI][4];
    #pragma unroll
    for (int mi = 0; mi < 4; mi++)
        #pragma unroll
        for (int ni = 0; ni < NI; ni++)
            #pragma unroll
            for (int r = 0; r < 4; r++) acc[mi][ni][r] = 0.f;

    GEMM_MAINLOOP(A, B, K, NI)

    if (MODE == 3) {
        float* C = (float*)Cv + sC * bz;
        #pragma unroll
        for (int mi = 0; mi < 4; mi++) {
            const int row0 = m0 + wm0 + mi * 16 + g;
            const float i0 = 1.0f / rowsum[row0];
            const float i8 = 1.0f / rowsum[row0 + 8];
            #pragma unroll
            for (int ni = 0; ni < NI; ni++) {
                const int col = n0 + wn0 + ni * 8 + 2 * t;
                *(float2*)(C + (long long)row0 * ldc + col) =
                    make_float2(acc[mi][ni][0] * i0, acc[mi][ni][1] * i0);
                *(float2*)(C + (long long)(row0 + 8) * ldc + col) =
                    make_float2(acc[mi][ni][2] * i8, acc[mi][ni][3] * i8);
            }
        }
    } else {
        __half* C = (__half*)Cv + sC * bz;
        #pragma unroll
        for (int mi = 0; mi < 4; mi++) {
            const int row0 = m0 + wm0 + mi * 16 + g;
            float s0 = 0.f, s8 = 0.f;
            #pragma unroll
            for (int ni = 0; ni < NI; ni++) {
                uint32_t u01 = pack2(__expf(alpha * acc[mi][ni][0]),
                                     __expf(alpha * acc[mi][ni][1]));
                uint32_t u23 = pack2(__expf(alpha * acc[mi][ni][2]),
                                     __expf(alpha * acc[mi][ni][3]));
                float2 f01 = unpack2(u01), f23 = unpack2(u23);
                s0 += f01.x + f01.y;  s8 += f23.x + f23.y;
                const int colm = n0 + wn0 + (ni >> 1) * 16 + 4 * t + 2 * (ni & 1);
                *(uint32_t*)(C + (long long)row0 * ldc + colm)       = u01;
                *(uint32_t*)(C + (long long)(row0 + 8) * ldc + colm) = u23;
            }
            s0 += __shfl_xor_sync(0xffffffffu, s0, 1);
            s0 += __shfl_xor_sync(0xffffffffu, s0, 2);
            s8 += __shfl_xor_sync(0xffffffffu, s8, 1);
            s8 += __shfl_xor_sync(0xffffffffu, s8, 2);
            if (t == 0) {
                atomicAdd(&rowsum[row0], s0);
                atomicAdd(&rowsum[row0 + 8], s8);
            }
        }
    }
}

// ---------------------------------------------------------------------------
// x (f32) -> fp16 with sigma16 permutation per 16-group
// ---------------------------------------------------------------------------
__global__ __launch_bounds__(256)
void convert_sigma16(const float4* __restrict__ in, uint4* __restrict__ out, int n16)
{
    int i = blockIdx.x * 256 + threadIdx.x;
    if (i < n16) {
        float4 v0 = in[i * 4 + 0], v1 = in[i * 4 + 1];
        float4 v2 = in[i * 4 + 2], v3 = in[i * 4 + 3];
        uint4 o0, o1;
        o0.x = pack2(v0.x, v0.y);   // 0,1
        o0.y = pack2(v2.x, v2.y);   // 8,9
        o0.z = pack2(v0.z, v0.w);   // 2,3
        o0.w = pack2(v2.z, v2.w);   // 10,11
        o1.x = pack2(v1.x, v1.y);   // 4,5
        o1.y = pack2(v3.x, v3.y);   // 12,13
        o1.z = pack2(v1.z, v1.w);   // 6,7
        o1.w = pack2(v3.z, v3.w);   // 14,15
        out[i * 2]     = o0;
        out[i * 2 + 1] = o1;
    }
}

// ---------------------------------------------------------------------------
// Transpose f32 -> fp16 with sigma16 on the output-column (k) dim.
// One launch handles all three weight matrices via blockIdx.z.
// ---------------------------------------------------------------------------
__global__ __launch_bounds__(256)
void transpose_sigma16_w(const float* __restrict__ Wq,
                         const float* __restrict__ Wk,
                         const float* __restrict__ Wv,
                         __half* __restrict__ oq,
                         __half* __restrict__ ok,
                         __half* __restrict__ ov,
                         int R, int Cc)
{
    __shared__ float tbuf[32][33];
    const int z = blockIdx.z;
    const float* in = (z == 0) ? Wq : (z == 1) ? Wk : Wv;
    __half* out     = (z == 0) ? oq : (z == 1) ? ok : ov;
    const int c0 = blockIdx.x * 32, r0 = blockIdx.y * 32;
    const int x = threadIdx.x, y = threadIdx.y;   // (32, 8)
    #pragma unroll
    for (int i = 0; i < 32; i += 8)
        tbuf[y + i][x] = in[(long long)(r0 + y + i) * Cc + c0 + x];
    __syncthreads();
    const int sx = sig16pos(x);
    #pragma unroll
    for (int i = 0; i < 32; i += 8)
        out[(long long)(c0 + y + i) * R + r0 + sx] = __float2half_rn(tbuf[x][y + i]);
}

__global__ __launch_bounds__(256)
void zero_kernel(float* __restrict__ p, int n)
{
    int i = blockIdx.x * 256 + threadIdx.x;
    if (i < n) p[i] = 0.f;
}

// ---------------------------------------------------------------------------
extern "C" void kernel_launch(void* const* d_in, const int* in_sizes, int n_in,
                              void* d_out, int out_size)
{
    const float* x  = (const float*)d_in[0];
    const float* Wq = (const float*)d_in[1];
    const float* bq = (const float*)d_in[2];
    const float* Wk = (const float*)d_in[3];
    const float* bk = (const float*)d_in[4];
    const float* Wv = (const float*)d_in[5];
    const float* bv = (const float*)d_in[6];
    float* out = (float*)d_out;

    __half *xc, *wqt, *wkt, *wvt, *q, *k, *vt, *p;
    float *rs;
    cudaGetSymbolAddress((void**)&xc,  g_xc);
    cudaGetSymbolAddress((void**)&wqt, g_wqt);
    cudaGetSymbolAddress((void**)&wkt, g_wkt);
    cudaGetSymbolAddress((void**)&wvt, g_wvt);
    cudaGetSymbolAddress((void**)&q,   g_q);
    cudaGetSymbolAddress((void**)&k,   g_k);
    cudaGetSymbolAddress((void**)&vt,  g_vt);
    cudaGetSymbolAddress((void**)&p,   g_p);
    cudaGetSymbolAddress((void**)&rs,  g_rs);

    cudaFuncSetAttribute(qkv_gemm,
                         cudaFuncAttributeMaxDynamicSharedMemorySize, SMEM_FOR(8));
    cudaFuncSetAttribute(gemm_mma<2, 8>,
                         cudaFuncAttributeMaxDynamicSharedMemorySize, SMEM_FOR(8));
    cudaFuncSetAttribute(gemm_mma<3, 4>,
                         cudaFuncAttributeMaxDynamicSharedMemorySize, SMEM_FOR(4));

    // 0) zero rowsums + convert x (fp16 + sigma16)
    zero_kernel<<<(BATCH * SEQ + 255) / 256, 256>>>(rs, BATCH * SEQ);
    convert_sigma16<<<(BATCH * SEQ * FEAT / 16 + 255) / 256, 256>>>(
        (const float4*)x, (uint4*)xc, BATCH * SEQ * FEAT / 16);

    // 1) W transposes (fp16 + sigma16 on f), one launch for all three
    dim3 tw(HID / 32, FEAT / 32, 3);
    transpose_sigma16_w<<<tw, dim3(32, 8)>>>(Wq, Wk, Wv, wqt, wkt, wvt, FEAT, HID);

    // 2) Merged QKV projections (z: 0=Q, 1=K, 2=V->V^T), BN=256
    dim3 gqkv(HID / 256, (BATCH * SEQ) / GBM, 3);
    qkv_gemm<<<gqkv, 256, SMEM_FOR(8)>>>(xc, wqt, wkt, wvt, bq, bk, bv, q, k, vt);

    // 3) p = exp((Q K^T)/32) (fp16, sigma16-stored) + rowsums, BN=256
    dim3 gs(SEQ / 256, SEQ / GBM, BATCH);
    gemm_mma<2, 8><<<gs, 256, SMEM_FOR(8)>>>(q, k, p, rs, HID, SEQ, 1.0f / 32.0f,
                                             (long long)SEQ * HID,
                                             (long long)SEQ * HID,
                                             (long long)SEQ * SEQ);

    // 4) out = (P V) / rowsum, BN=128, 2 CTAs/SM
    dim3 go(HID / 128, SEQ / GBM, BATCH);
    gemm_mma<3, 4><<<go, 256, SMEM_FOR(4)>>>(p, vt, out, rs, SEQ, HID, 1.0f,
                                             (long long)SEQ * SEQ,
                                             (long long)HID * SEQ,
                                             (long long)SEQ * HID);
}

// round 17
// speedup vs baseline: 2.3813x; 1.0373x over previous
#include <cuda_runtime.h>
#include <cuda_fp16.h>
#include <cstdint>
#include <math.h>

#define BATCH 4
#define SEQ   4096
#define FEAT  1024
#define HID   1024

// ---------------------------------------------------------------------------
// Scratch (device globals). All fp16 MMA operands stored sigma16-permuted
// within 16-k-groups: mem order [0,1,8,9, 2,3,10,11, 4,5,12,13, 6,7,14,15]
// ---------------------------------------------------------------------------
__device__ __half g_xc [BATCH * SEQ * FEAT];   // x   (fp16, sig-f)   32 MB
__device__ __half g_wqt[FEAT * HID];           // Wq^T (fp16, sig-f)   2 MB
__device__ __half g_wkt[FEAT * HID];           // Wk^T (fp16, sig-f)   2 MB
__device__ __half g_wvt[FEAT * HID];           // Wv^T (fp16, sig-f)   2 MB
__device__ __half g_q  [BATCH * SEQ * HID];    // Q (fp16, sig-h)     32 MB
__device__ __half g_k  [BATCH * SEQ * HID];    // K (fp16, sig-h)     32 MB
__device__ __half g_vt [BATCH * HID * SEQ];    // V^T (fp16, sig-s)   32 MB
__device__ __half g_p  [(size_t)BATCH * SEQ * SEQ]; // exp(scores)   128 MB
__device__ float  g_rs [BATCH * SEQ];          // row sums of exp

// ---------------------------------------------------------------------------
__device__ __forceinline__ uint32_t pack2(float lo, float hi) {
    __half2 h = __floats2half2_rn(lo, hi);
    return *reinterpret_cast<uint32_t*>(&h);
}
__device__ __forceinline__ float2 unpack2(uint32_t u) {
    __half2 h = *reinterpret_cast<__half2*>(&u);
    return __half22float2(h);
}

__device__ __forceinline__ void cp_async16(uint32_t s, const void* g) {
    asm volatile("cp.async.cg.shared.global [%0], [%1], 16;"
                 :: "r"(s), "l"(__cvta_generic_to_global(g)) : "memory");
}

__device__ __forceinline__ uint32_t smem_u32(const void* p) {
    uint32_t a;
    asm("{ .reg .u64 t; cvta.to.shared.u64 t, %1; cvt.u32.u64 %0, t; }"
        : "=r"(a) : "l"(p));
    return a;
}

// sigma16 position of logical index s within its 16-group
__device__ __forceinline__ int sig16pos(int s) {
    int q = s & 15;
    return (s & ~15) | (4 * ((q & 7) >> 1) + 2 * (q >> 3) + (q & 1));
}

__device__ __forceinline__ void mma_f16(float* c, uint32_t a0, uint32_t a1,
                                        uint32_t a2, uint32_t a3,
                                        uint32_t b0, uint32_t b1) {
    asm volatile(
        "mma.sync.aligned.m16n8k16.row.col.f32.f16.f16.f32 "
        "{%0,%1,%2,%3}, {%4,%5,%6,%7}, {%8,%9}, {%0,%1,%2,%3};"
        : "+f"(c[0]), "+f"(c[1]), "+f"(c[2]), "+f"(c[3])
        : "r"(a0), "r"(a1), "r"(a2), "r"(a3), "r"(b0), "r"(b1));
}

// ---------------------------------------------------------------------------
// Tile geometry. BM=128, BN=128 (NI=4), BK=64 halves, 3 stages, 256 threads
// (8 warps 2x4 -> 64x32 per warp), 2 CTAs/SM. XOR-swizzled smem:
//   store: 16B chunk ch of row r -> chunk (ch ^ (2*(r&3)))
//   read : fragment slot (4kk+t) of row r -> halves 16*(kk ^ (r&3)) + 4t
// ---------------------------------------------------------------------------
#define GBM 128
#define GBK 64
#define GST 3
#define SROW 64
#define A_HALVES (GBM * SROW)                   // 8192
#define SMEM_FOR(NI) (GST * (A_HALVES + (NI) * 32 * SROW) * 2)

// Mainloop: computes acc[4][NI_][4] for tile (m0, n0) of A x B^T.
#define GEMM_MAINLOOP(A_, B_, K_, NI_)                                         \
    constexpr int BHALVES_ = (NI_) * 32 * SROW;                                \
    constexpr int STGH_ = A_HALVES + BHALVES_;                                 \
    const int NITER = (K_) / GBK;                                              \
    auto load_stage = [&](int c) {                                             \
        const int slot = c % GST;                                              \
        const uint32_t s_a = sbase + slot * STGH_ * 2;                         \
        const uint32_t s_b = s_a + A_HALVES * 2;                               \
        const long long koff = (long long)c * GBK;                             \
        _Pragma("unroll")                                                      \
        for (int i = 0; i < 4; i++) {                                          \
            int s = tid + i * 256;                                             \
            int row = s >> 3, ch = s & 7;                                      \
            int chs = ch ^ (2 * (row & 3));                                    \
            cp_async16(s_a + (uint32_t)(row * 128 + chs * 16),                 \
                       (A_) + (long long)(m0 + row) * (K_) + koff + ch * 8);   \
        }                                                                      \
        _Pragma("unroll")                                                      \
        for (int i = 0; i < (NI_); i++) {                                      \
            int s = tid + i * 256;                                             \
            int row = s >> 3, ch = s & 7;                                      \
            int chs = ch ^ (2 * (row & 3));                                    \
            cp_async16(s_b + (uint32_t)(row * 128 + chs * 16),                 \
                       (B_) + (long long)(n0 + row) * (K_) + koff + ch * 8);   \
        }                                                                      \
        asm volatile("cp.async.commit_group;" ::: "memory");                   \
    };                                                                         \
    load_stage(0);                                                             \
    if (NITER > 1) load_stage(1);                                              \
    for (int it = 0; it < NITER; it++) {                                       \
        if (it < NITER - 1)                                                    \
            asm volatile("cp.async.wait_group 1;" ::: "memory");               \
        else                                                                   \
            asm volatile("cp.async.wait_group 0;" ::: "memory");               \
        __syncthreads();                                                       \
        if (it + 2 < NITER) load_stage(it + 2);                                \
        const int slot = it % GST;                                             \
        const __half* as = smh + slot * STGH_ + wm0 * SROW;                    \
        const __half* bs = smh + slot * STGH_ + A_HALVES + wn0 * SROW;         \
        _Pragma("unroll")                                                      \
        for (int kk = 0; kk < 4; kk++) {                                       \
            const int fo = 16 * (kk ^ (g & 3)) + 4 * t;                        \
            uint2 a2[4][2];                                                    \
            _Pragma("unroll")                                                  \
            for (int mi = 0; mi < 4; mi++) {                                   \
                const __half* ap = as + (mi * 16 + g) * SROW + fo;             \
                a2[mi][0] = *(const uint2*)ap;                                 \
                a2[mi][1] = *(const uint2*)(ap + 8 * SROW);                    \
            }                                                                  \
            uint2 b2[NI_];                                                     \
            _Pragma("unroll")                                                  \
            for (int ni = 0; ni < (NI_); ni++)                                 \
                b2[ni] = *(const uint2*)(bs + (ni * 8 + g) * SROW + fo);       \
            _Pragma("unroll")                                                  \
            for (int mi = 0; mi < 4; mi++)                                     \
                _Pragma("unroll")                                              \
                for (int ni = 0; ni < (NI_); ni++)                             \
                    mma_f16(acc[mi][ni],                                       \
                            a2[mi][0].x, a2[mi][1].x, a2[mi][0].y, a2[mi][1].y,\
                            b2[ni].x, b2[ni].y);                               \
        }                                                                      \
    }

// ---------------------------------------------------------------------------
// Merged QKV projection (NI=4, 2 CTAs/SM): grid.z selects Q / K / V->V^T.
// z<2: fp16 + sigma16 store. z==2: transposed store (V^T, sigma16 on s)
// staged through smem (128 rows) with coalesced 256B row write-out.
// ---------------------------------------------------------------------------
__global__ __launch_bounds__(256, 2)
void qkv_gemm(const __half* __restrict__ A,
              const __half* __restrict__ Bq, const __half* __restrict__ Bk,
              const __half* __restrict__ Bv,
              const float* __restrict__ bq_, const float* __restrict__ bk_,
              const float* __restrict__ bv_,
              __half* __restrict__ q, __half* __restrict__ k,
              __half* __restrict__ vt)
{
    extern __shared__ __half smh[];
    const uint32_t sbase = smem_u32(smh);

    const int tid = threadIdx.x;
    const int wid = tid >> 5, lane = tid & 31;
    const int g = lane >> 2, t = lane & 3;
    const int wm = wid >> 2, wn = wid & 3;
    const int wm0 = wm * 64, wn0 = wn * 32;

    const int z = blockIdx.z;
    const __half* B    = (z == 0) ? Bq  : (z == 1) ? Bk  : Bv;
    const float*  bias = (z == 0) ? bq_ : (z == 1) ? bk_ : bv_;

    const int m0 = blockIdx.y * GBM;
    const int n0 = blockIdx.x * 128;

    float acc[4][4][4];
    #pragma unroll
    for (int mi = 0; mi < 4; mi++)
        #pragma unroll
        for (int ni = 0; ni < 4; ni++)
            #pragma unroll
            for (int r = 0; r < 4; r++) acc[mi][ni][r] = 0.f;

    GEMM_MAINLOOP(A, B, FEAT, 4)

    if (z < 2) {
        __half* C = (z == 0) ? q : k;
        #pragma unroll
        for (int mi = 0; mi < 4; mi++) {
            const int row0 = m0 + wm0 + mi * 16 + g;
            #pragma unroll
            for (int ni = 0; ni < 4; ni++) {
                const float2 bv2 = *(const float2*)(bias + n0 + wn0 + ni * 8 + 2 * t);
                uint32_t u01 = pack2(acc[mi][ni][0] + bv2.x, acc[mi][ni][1] + bv2.y);
                uint32_t u23 = pack2(acc[mi][ni][2] + bv2.x, acc[mi][ni][3] + bv2.y);
                const int colm = n0 + wn0 + (ni >> 1) * 16 + 4 * t + 2 * (ni & 1);
                *(uint32_t*)(C + (long long)row0 * HID + colm)       = u01;
                *(uint32_t*)(C + (long long)(row0 + 8) * HID + colm) = u23;
            }
        }
    } else {
        // ---- V: transpose-in-smem epilogue, write V^T (sigma16 on s) ----
        const int TSTR = 136;                        // padded row stride (halves)
        __syncthreads();                             // mainloop smem reads done
        #pragma unroll
        for (int mi = 0; mi < 4; mi++) {
            const int s0 = wm0 + mi * 16 + g;
            const int sp0 = sig16pos(s0), sp8 = sig16pos(s0 + 8);
            #pragma unroll
            for (int ni = 0; ni < 4; ni++) {
                const int h0 = wn0 + ni * 8 + 2 * t;
                const float2 bv2 = *(const float2*)(bias + n0 + h0);
                smh[h0 * TSTR + sp0]       = __float2half_rn(acc[mi][ni][0] + bv2.x);
                smh[(h0 + 1) * TSTR + sp0] = __float2half_rn(acc[mi][ni][1] + bv2.y);
                smh[h0 * TSTR + sp8]       = __float2half_rn(acc[mi][ni][2] + bv2.x);
                smh[(h0 + 1) * TSTR + sp8] = __float2half_rn(acc[mi][ni][3] + bv2.y);
            }
        }
        __syncthreads();
        const int bzb = m0 >> 12;                    // batch index
        const int sg  = m0 & 4095;                   // s offset within batch
        __half* vtb = vt + (size_t)bzb * HID * SEQ + sg;
        const int hh  = lane >> 4;                   // half-warp row select
        const int off = lane & 15;                   // 16B chunk within row
        #pragma unroll
        for (int r = 0; r < 16; r += 2) {            // 8 warps x 16 rows = 128
            const int h = wid * 16 + r + hh;
            uint4 val = *(uint4*)(smh + h * TSTR + off * 8);
            *(uint4*)(vtb + (size_t)(n0 + h) * SEQ + off * 8) = val;
        }
    }
}

// ---------------------------------------------------------------------------
// Attention GEMMs (NI=4, 2 CTAs/SM).
//   MODE 2 = exp(alpha*acc) -> fp16 sigma16-store + rowsum (probs)
//   MODE 3 = acc / rowsum, f32 natural store (output)
// ---------------------------------------------------------------------------
template <int MODE>
__global__ __launch_bounds__(256, 2)
void gemm_mma(const __half* __restrict__ A, const __half* __restrict__ B,
              void* __restrict__ Cv, float* __restrict__ rowsum,
              int K, int ldc, float alpha,
              long long sA, long long sB, long long sC)
{
    extern __shared__ __half smh[];
    const uint32_t sbase = smem_u32(smh);

    const int tid = threadIdx.x;
    const int wid = tid >> 5, lane = tid & 31;
    const int g = lane >> 2, t = lane & 3;
    const int wm = wid >> 2, wn = wid & 3;
    const int wm0 = wm * 64, wn0 = wn * 32;

    const int bz = blockIdx.z;
    A += sA * bz; B += sB * bz;
    rowsum += (long long)SEQ * bz;
    const int m0 = blockIdx.y * GBM;
    const int n0 = blockIdx.x * 128;

    float acc[4][4][4];
    #pragma unroll
    for (int mi = 0; mi < 4; mi++)
        #pragma unroll
        for (int ni = 0; ni < 4; ni++)
            #pragma unroll
            for (int r = 0; r < 4; r++) acc[mi][ni][r] = 0.f;

    GEMM_MAINLOOP(A, B, K, 4)

    if (MODE == 3) {
        float* C = (float*)Cv + sC * bz;
        #pragma unroll
        for (int mi = 0; mi < 4; mi++) {
            const int row0 = m0 + wm0 + mi * 16 + g;
            const float i0 = 1.0f / rowsum[row0];
            const float i8 = 1.0f / rowsum[row0 + 8];
            #pragma unroll
            for (int ni = 0; ni < 4; ni++) {
                const int col = n0 + wn0 + ni * 8 + 2 * t;
                *(float2*)(C + (long long)row0 * ldc + col) =
                    make_float2(acc[mi][ni][0] * i0, acc[mi][ni][1] * i0);
                *(float2*)(C + (long long)(row0 + 8) * ldc + col) =
                    make_float2(acc[mi][ni][2] * i8, acc[mi][ni][3] * i8);
            }
        }
    } else {
        __half* C = (__half*)Cv + sC * bz;
        #pragma unroll
        for (int mi = 0; mi < 4; mi++) {
            const int row0 = m0 + wm0 + mi * 16 + g;
            float s0 = 0.f, s8 = 0.f;
            #pragma unroll
            for (int ni = 0; ni < 4; ni++) {
                uint32_t u01 = pack2(__expf(alpha * acc[mi][ni][0]),
                                     __expf(alpha * acc[mi][ni][1]));
                uint32_t u23 = pack2(__expf(alpha * acc[mi][ni][2]),
                                     __expf(alpha * acc[mi][ni][3]));
                float2 f01 = unpack2(u01), f23 = unpack2(u23);
                s0 += f01.x + f01.y;  s8 += f23.x + f23.y;
                const int colm = n0 + wn0 + (ni >> 1) * 16 + 4 * t + 2 * (ni & 1);
                *(uint32_t*)(C + (long long)row0 * ldc + colm)       = u01;
                *(uint32_t*)(C + (long long)(row0 + 8) * ldc + colm) = u23;
            }
            s0 += __shfl_xor_sync(0xffffffffu, s0, 1);
            s0 += __shfl_xor_sync(0xffffffffu, s0, 2);
            s8 += __shfl_xor_sync(0xffffffffu, s8, 1);
            s8 += __shfl_xor_sync(0xffffffffu, s8, 2);
            if (t == 0) {
                atomicAdd(&rowsum[row0], s0);
                atomicAdd(&rowsum[row0 + 8], s8);
            }
        }
    }
}

// ---------------------------------------------------------------------------
// x (f32) -> fp16 with sigma16 permutation per 16-group
// ---------------------------------------------------------------------------
__global__ __launch_bounds__(256)
void convert_sigma16(const float4* __restrict__ in, uint4* __restrict__ out, int n16)
{
    int i = blockIdx.x * 256 + threadIdx.x;
    if (i < n16) {
        float4 v0 = in[i * 4 + 0], v1 = in[i * 4 + 1];
        float4 v2 = in[i * 4 + 2], v3 = in[i * 4 + 3];
        uint4 o0, o1;
        o0.x = pack2(v0.x, v0.y);   // 0,1
        o0.y = pack2(v2.x, v2.y);   // 8,9
        o0.z = pack2(v0.z, v0.w);   // 2,3
        o0.w = pack2(v2.z, v2.w);   // 10,11
        o1.x = pack2(v1.x, v1.y);   // 4,5
        o1.y = pack2(v3.x, v3.y);   // 12,13
        o1.z = pack2(v1.z, v1.w);   // 6,7
        o1.w = pack2(v3.z, v3.w);   // 14,15
        out[i * 2]     = o0;
        out[i * 2 + 1] = o1;
    }
}

// ---------------------------------------------------------------------------
// Transpose f32 -> fp16 with sigma16 on the output-column (k) dim.
// One launch handles all three weight matrices via blockIdx.z.
// ---------------------------------------------------------------------------
__global__ __launch_bounds__(256)
void transpose_sigma16_w(const float* __restrict__ Wq,
                         const float* __restrict__ Wk,
                         const float* __restrict__ Wv,
                         __half* __restrict__ oq,
                         __half* __restrict__ ok,
                         __half* __restrict__ ov,
                         int R, int Cc)
{
    __shared__ float tbuf[32][33];
    const int z = blockIdx.z;
    const float* in = (z == 0) ? Wq : (z == 1) ? Wk : Wv;
    __half* out     = (z == 0) ? oq : (z == 1) ? ok : ov;
    const int c0 = blockIdx.x * 32, r0 = blockIdx.y * 32;
    const int x = threadIdx.x, y = threadIdx.y;   // (32, 8)
    #pragma unroll
    for (int i = 0; i < 32; i += 8)
        tbuf[y + i][x] = in[(long long)(r0 + y + i) * Cc + c0 + x];
    __syncthreads();
    const int sx = sig16pos(x);
    #pragma unroll
    for (int i = 0; i < 32; i += 8)
        out[(long long)(c0 + y + i) * R + r0 + sx] = __float2half_rn(tbuf[x][y + i]);
}

__global__ __launch_bounds__(256)
void zero_kernel(float* __restrict__ p, int n)
{
    int i = blockIdx.x * 256 + threadIdx.x;
    if (i < n) p[i] = 0.f;
}

// ---------------------------------------------------------------------------
extern "C" void kernel_launch(void* const* d_in, const int* in_sizes, int n_in,
                              void* d_out, int out_size)
{
    const float* x  = (const float*)d_in[0];
    const float* Wq = (const float*)d_in[1];
    const float* bq = (const float*)d_in[2];
    const float* Wk = (const float*)d_in[3];
    const float* bk = (const float*)d_in[4];
    const float* Wv = (const float*)d_in[5];
    const float* bv = (const float*)d_in[6];
    float* out = (float*)d_out;

    __half *xc, *wqt, *wkt, *wvt, *q, *k, *vt, *p;
    float *rs;
    cudaGetSymbolAddress((void**)&xc,  g_xc);
    cudaGetSymbolAddress((void**)&wqt, g_wqt);
    cudaGetSymbolAddress((void**)&wkt, g_wkt);
    cudaGetSymbolAddress((void**)&wvt, g_wvt);
    cudaGetSymbolAddress((void**)&q,   g_q);
    cudaGetSymbolAddress((void**)&k,   g_k);
    cudaGetSymbolAddress((void**)&vt,  g_vt);
    cudaGetSymbolAddress((void**)&p,   g_p);
    cudaGetSymbolAddress((void**)&rs,  g_rs);

    cudaFuncSetAttribute(qkv_gemm,
                         cudaFuncAttributeMaxDynamicSharedMemorySize, SMEM_FOR(4));
    cudaFuncSetAttribute(gemm_mma<2>,
                         cudaFuncAttributeMaxDynamicSharedMemorySize, SMEM_FOR(4));
    cudaFuncSetAttribute(gemm_mma<3>,
                         cudaFuncAttributeMaxDynamicSharedMemorySize, SMEM_FOR(4));

    // 0) zero rowsums + convert x (fp16 + sigma16)
    zero_kernel<<<(BATCH * SEQ + 255) / 256, 256>>>(rs, BATCH * SEQ);
    convert_sigma16<<<(BATCH * SEQ * FEAT / 16 + 255) / 256, 256>>>(
        (const float4*)x, (uint4*)xc, BATCH * SEQ * FEAT / 16);

    // 1) W transposes (fp16 + sigma16 on f), one launch for all three
    dim3 tw(HID / 32, FEAT / 32, 3);
    transpose_sigma16_w<<<tw, dim3(32, 8)>>>(Wq, Wk, Wv, wqt, wkt, wvt, FEAT, HID);

    // 2) Merged QKV projections (z: 0=Q, 1=K, 2=V->V^T), BN=128, 2 CTAs/SM
    dim3 gqkv(HID / 128, (BATCH * SEQ) / GBM, 3);
    qkv_gemm<<<gqkv, 256, SMEM_FOR(4)>>>(xc, wqt, wkt, wvt, bq, bk, bv, q, k, vt);

    // 3) p = exp((Q K^T)/32) + rowsums, BN=128, 2 CTAs/SM
    dim3 gs(SEQ / 128, SEQ / GBM, BATCH);
    gemm_mma<2><<<gs, 256, SMEM_FOR(4)>>>(q, k, p, rs, HID, SEQ, 1.0f / 32.0f,
                                          (long long)SEQ * HID,
                                          (long long)SEQ * HID,
                                          (long long)SEQ * SEQ);

    // 4) out = (P V) / rowsum, BN=128, 2 CTAs/SM
    dim3 go(HID / 128, SEQ / GBM, BATCH);
    gemm_mma<3><<<go, 256, SMEM_FOR(4)>>>(p, vt, out, rs, SEQ, HID, 1.0f,
                                          (long long)SEQ * SEQ,
                                          (long long)HID * SEQ,
                                          (long long)SEQ * HID);
}